// round 12
// baseline (speedup 1.0000x reference)
#include <cuda_runtime.h>
#include <cuda_fp16.h>
#include <cstdint>
#include <math.h>

#define NEGV (-1000000000.0f)
#define FLT_MAXV 3.402823466e38f

// ---------------- output layout ----------------
static const long OFF_LOGITS = 0;
static const long OFF_LP     = 385024;
static const long OFF_ACT    = 393216;
static const long OFF_VAL    = 401408;

#define SWZ128(x) ((x) ^ (((x) >> 3) & 0x70))

__device__ __forceinline__ uint32_t smem_to_u32(const void* p) {
    uint32_t a;
    asm("{ .reg .u64 t; cvta.to.shared.u64 t, %1; cvt.u32.u64 %0, t; }" : "=r"(a) : "l"(p));
    return a;
}
__device__ __forceinline__ void cp16(uint32_t sad, const void* gad) {
    asm volatile("cp.async.cg.shared.global [%0], [%1], 16;" :: "r"(sad), "l"(gad) : "memory");
}
__device__ __forceinline__ void ldm_x4(uint32_t* r, uint32_t addr) {
    asm volatile("ldmatrix.sync.aligned.m8n8.x4.shared.b16 {%0,%1,%2,%3}, [%4];"
                 : "=r"(r[0]), "=r"(r[1]), "=r"(r[2]), "=r"(r[3]) : "r"(addr));
}
__device__ __forceinline__ void mma16816(float* c, const uint32_t* a, const uint32_t* b) {
    asm volatile("mma.sync.aligned.m16n8k16.row.col.f32.f16.f16.f32 "
                 "{%0,%1,%2,%3}, {%4,%5,%6,%7}, {%8,%9}, {%0,%1,%2,%3};"
                 : "+f"(c[0]), "+f"(c[1]), "+f"(c[2]), "+f"(c[3])
                 : "r"(a[0]), "r"(a[1]), "r"(a[2]), "r"(a[3]), "r"(b[0]), "r"(b[1]));
}

// ---------------- scratch (device globals) ----------------
__device__ __half g_A0h[4096L * 7168];
__device__ __half g_A0l[4096L * 7168];
__device__ __half g_B0h[1024L * 7168];
__device__ __half g_B0l[1024L * 7168];
__device__ __half g_B1h[1024L * 1024];
__device__ __half g_B1l[1024L * 1024];
__device__ __half g_B2h[1024L * 1024];
__device__ __half g_B2l[1024L * 1024];
__device__ __half g_Bhh[128L * 1024];
__device__ __half g_Bhl[128L * 1024];
__device__ float  g_bh[128];
__device__ float  g_Y[4096L * 1024];
__device__ __half g_Xh[4096L * 1024];
__device__ __half g_Xl[4096L * 1024];
__device__ int    g_cnt[32];             // zero-init; self-resetting per launch

// ---------------- conversion kernels ----------------
// one block per row; float2 reads, half2 writes, no div/mod
__global__ void split_obs_k(const float* __restrict__ obs) {
    const int r   = blockIdx.x;
    const int tid = threadIdx.x;   // 256
    const float2* src = (const float2*)(obs + (size_t)r * 7150);   // 8B aligned
    __half2* dh = (__half2*)(g_A0h + (size_t)r * 7168);
    __half2* dl = (__half2*)(g_A0l + (size_t)r * 7168);
    #pragma unroll 4
    for (int i = tid; i < 3575; i += 256) {
        float2 v = src[i];
        __half hx = __float2half(v.x);
        __half hy = __float2half(v.y);
        dh[i] = __halves2half2(hx, hy);
        dl[i] = __halves2half2(__float2half(v.x - __half2float(hx)),
                               __float2half(v.y - __half2float(hy)));
    }
    if (tid < 9) {   // pad cols 7150..7167
        __half2 z = __float2half2_rn(0.0f);
        dh[3575 + tid] = z;
        dl[3575 + tid] = z;
    }
}

// W (K x N fp32) -> Bt hi/lo (N x Kpad fp16), transposed + split
__global__ void transpose_split_k(const float* __restrict__ W,
                                  __half* __restrict__ Bh,
                                  __half* __restrict__ Bl,
                                  int K, int Kpad, int N) {
    __shared__ float t[32][33];
    int k0 = blockIdx.x * 32, n0 = blockIdx.y * 32;
    int tx = threadIdx.x, ty = threadIdx.y;   // (32, 8)
    #pragma unroll
    for (int d = 0; d < 4; d++) {
        int k = k0 + ty + d * 8;
        t[ty + d * 8][tx] = (k < K) ? W[(size_t)k * N + n0 + tx] : 0.0f;
    }
    __syncthreads();
    #pragma unroll
    for (int d = 0; d < 4; d++) {
        int n = n0 + ty + d * 8;
        int k = k0 + tx;
        float x = t[tx][ty + d * 8];
        __half h = __float2half(x);
        Bh[(size_t)n * Kpad + k] = h;
        Bl[(size_t)n * Kpad + k] = __float2half(x - __half2float(h));
    }
}

__global__ void pack_head_k(const float* __restrict__ Wp, const float* __restrict__ bp,
                            const float* __restrict__ Wv, const float* __restrict__ bv) {
    int idx = blockIdx.x * blockDim.x + threadIdx.x;
    if (idx < 128 * 1024) {
        int n = idx / 1024;
        int k = idx % 1024;
        float x = 0.0f;
        if (n < 94)       x = Wp[(size_t)k * 94 + n];
        else if (n == 94) x = Wv[k];
        __half h = __float2half(x);
        g_Bhh[idx] = h;
        g_Bhl[idx] = __float2half(x - __half2float(h));
    }
    if (idx < 128) {
        float v = 0.0f;
        if (idx < 94)       v = bp[idx];
        else if (idx == 94) v = bv[0];
        g_bh[idx] = v;
    }
}

// ---------------- HMMA GEMM + fused LN epilogue ----------------
// C(MxN) = A(MxK) @ Bt(NxK)^T + bias; 3-product fp16 split (R6 optimum).
// CTA tile (IM*32) x 128, 8 warps, 3-stage cp.async, XOR-folded ldmatrix.
// If lnCnt != nullptr (N==1024): the last column-CTA of each 128-row block
// performs LayerNorm+ReLU+fp16-split for those rows (warp-per-row, two-pass,
// __ldcg) and writes Xh/Xl; counter self-resets for graph replay.
template<int IM>
__global__ void __launch_bounds__(256, 2)
gemm_hmma(const __half* __restrict__ Ahi, const __half* __restrict__ Alo,
          const __half* __restrict__ Bhi, const __half* __restrict__ Blo,
          const float* __restrict__ bias, float* __restrict__ C, int N, int K,
          const float* __restrict__ gamma, const float* __restrict__ beta,
          __half* __restrict__ Xh, __half* __restrict__ Xl, int* lnCnt)
{
    constexpr int BM = IM * 32;
    constexpr uint32_t A_BYTES = (uint32_t)BM * 128;
    constexpr uint32_t SSTRIDE = A_BYTES + 16384u;

    extern __shared__ char smem_raw[];
    const uint32_t sbase = (smem_to_u32(smem_raw) + 127u) & ~127u;   // 128B aligned
    const int tid  = threadIdx.x;
    const int wid  = tid >> 5;
    const int lane = tid & 31;
    const int bm   = blockIdx.y * BM;
    const int bn   = blockIdx.x * 128;
    const int wm   = (wid >> 2) * (IM * 16);
    const int wn   = (wid & 3) * 32;

    const int niter = K >> 5;           // 32-wide k-chunks

    float acc[IM][4][4];
    #pragma unroll
    for (int im = 0; im < IM; im++)
        #pragma unroll
        for (int in = 0; in < 4; in++)
            #pragma unroll
            for (int j = 0; j < 4; j++) acc[im][in][j] = 0.0f;

    const int ldrow = tid >> 3;
    const int j7    = tid & 7;
    const int halfv = j7 >> 2;
    const int el16  = (j7 & 3) * 8;
    const uint32_t sAoff = SWZ128((uint32_t)(ldrow * 128 + j7 * 16));
    const uint32_t sBoff = A_BYTES + SWZ128((uint32_t)(ldrow * 128 + j7 * 16));
    const __half* Ag = (halfv ? Alo : Ahi) + (size_t)(bm + ldrow) * K + el16;
    const __half* Bg = (halfv ? Blo : Bhi) + (size_t)(bn + ldrow) * K + el16;
    const size_t gstepA = (size_t)32 * K;

    uint32_t so_ld = 0;
    auto load_stage = [&]() {
        #pragma unroll
        for (int j = 0; j < IM; j++)
            cp16(sbase + so_ld + sAoff + (uint32_t)j * 4096u, Ag + (size_t)j * gstepA);
        #pragma unroll
        for (int j = 0; j < 4; j++)
            cp16(sbase + so_ld + sBoff + (uint32_t)j * 4096u, Bg + (size_t)j * gstepA);
        Ag += 32; Bg += 32;
        so_ld += SSTRIDE;
        if (so_ld == 3 * SSTRIDE) so_ld = 0;
    };

    const int arow = wm + (lane & 15);
    const int asub = (lane >> 4) << 4;
    const int brow = wn + (lane & 7) + ((lane >> 4) << 3);
    const int bsub = ((lane >> 3) & 1) << 4;
    uint32_t offA[IM], offB[2];
    #pragma unroll
    for (int im = 0; im < IM; im++)
        offA[im] = SWZ128((uint32_t)(((arow + im * 16) << 7) + asub));
    #pragma unroll
    for (int ib = 0; ib < 2; ib++)
        offB[ib] = A_BYTES + SWZ128((uint32_t)(((brow + ib * 16) << 7) + bsub));

    load_stage();
    asm volatile("cp.async.commit_group;" ::: "memory");
    load_stage();
    asm volatile("cp.async.commit_group;" ::: "memory");

    uint32_t so_cm = 0;
    for (int t = 0; t < niter; t++) {
        asm volatile("cp.async.wait_group 1;" ::: "memory");
        __syncthreads();

        if (t + 2 < niter) load_stage();
        asm volatile("cp.async.commit_group;" ::: "memory");

        const uint32_t sa = sbase + so_cm;
        so_cm += SSTRIDE;
        if (so_cm == 3 * SSTRIDE) so_cm = 0;

        uint32_t aA[IM], aB[2];
        #pragma unroll
        for (int im = 0; im < IM; im++) aA[im] = sa + offA[im];
        #pragma unroll
        for (int ib = 0; ib < 2; ib++)  aB[ib] = sa + offB[ib];

        #pragma unroll
        for (int ks = 0; ks < 2; ks++) {
            const uint32_t kx = ks ? 32u : 0u;
            uint32_t bh[2][4], bl[2][4];
            #pragma unroll
            for (int ib = 0; ib < 2; ib++) {
                ldm_x4(bh[ib], aB[ib] ^ kx);
                ldm_x4(bl[ib], aB[ib] ^ (kx | 64u));
            }
            {
                uint32_t ah[IM][4];
                #pragma unroll
                for (int im = 0; im < IM; im++)
                    ldm_x4(ah[im], aA[im] ^ kx);
                #pragma unroll
                for (int im = 0; im < IM; im++)
                    #pragma unroll
                    for (int in = 0; in < 4; in++)
                        mma16816(acc[im][in], ah[im], &bh[in >> 1][(in & 1) * 2]);
                #pragma unroll
                for (int im = 0; im < IM; im++)
                    #pragma unroll
                    for (int in = 0; in < 4; in++)
                        mma16816(acc[im][in], ah[im], &bl[in >> 1][(in & 1) * 2]);
            }
            {
                uint32_t al[IM][4];
                #pragma unroll
                for (int im = 0; im < IM; im++)
                    ldm_x4(al[im], aA[im] ^ (kx | 64u));
                #pragma unroll
                for (int im = 0; im < IM; im++)
                    #pragma unroll
                    for (int in = 0; in < 4; in++)
                        mma16816(acc[im][in], al[im], &bh[in >> 1][(in & 1) * 2]);
            }
        }
    }

    // epilogue: bias + direct stores (fragment-native layout)
    #pragma unroll
    for (int in = 0; in < 4; in++) {
        int col = bn + wn + in * 8 + ((lane & 3) << 1);
        float bx = bias[col], by = bias[col + 1];
        #pragma unroll
        for (int im = 0; im < IM; im++) {
            int row = bm + wm + im * 16 + (lane >> 2);
            float2 v0 = { acc[im][in][0] + bx, acc[im][in][1] + by };
            float2 v1 = { acc[im][in][2] + bx, acc[im][in][3] + by };
            *(float2*)(C + (size_t)row * N + col)       = v0;
            *(float2*)(C + (size_t)(row + 8) * N + col) = v1;
        }
    }

    // ---- fused LayerNorm + ReLU + fp16 split (last column-CTA per row block) ----
    if (lnCnt != nullptr) {
        __threadfence();
        __syncthreads();
        __shared__ int stick;
        if (tid == 0) stick = atomicAdd(&lnCnt[blockIdx.y], 1);
        __syncthreads();
        if (stick == (int)gridDim.x - 1) {
            // warp-per-row, two-pass over N=1024 (256 float4 per row)
            for (int r = wid; r < BM; r += 8) {
                const float4* row4 = (const float4*)(C + (size_t)(bm + r) * 1024);
                float s = 0.0f, q = 0.0f;
                #pragma unroll
                for (int j = 0; j < 8; j++) {
                    float4 v = __ldcg(row4 + lane + j * 32);
                    s += v.x + v.y + v.z + v.w;
                    q += v.x * v.x + v.y * v.y + v.z * v.z + v.w * v.w;
                }
                #pragma unroll
                for (int o = 16; o; o >>= 1) {
                    s += __shfl_xor_sync(0xffffffffu, s, o);
                    q += __shfl_xor_sync(0xffffffffu, q, o);
                }
                float mm   = s * (1.0f / 1024.0f);
                float rstd = rsqrtf(q * (1.0f / 1024.0f) - mm * mm + 1e-5f);

                __half2* xh2 = (__half2*)(Xh + (size_t)(bm + r) * 1024);
                __half2* xl2 = (__half2*)(Xl + (size_t)(bm + r) * 1024);
                #pragma unroll
                for (int j = 0; j < 8; j++) {
                    int i4 = lane + j * 32;
                    float4 v  = __ldcg(row4 + i4);
                    float4 gv = *((const float4*)gamma + i4);
                    float4 bv = *((const float4*)beta  + i4);
                    float o0 = fmaxf(0.0f, (v.x - mm) * rstd * gv.x + bv.x);
                    float o1 = fmaxf(0.0f, (v.y - mm) * rstd * gv.y + bv.y);
                    float o2 = fmaxf(0.0f, (v.z - mm) * rstd * gv.z + bv.z);
                    float o3 = fmaxf(0.0f, (v.w - mm) * rstd * gv.w + bv.w);
                    __half h0 = __float2half(o0), h1 = __float2half(o1);
                    __half h2 = __float2half(o2), h3 = __float2half(o3);
                    xh2[i4 * 2]     = __halves2half2(h0, h1);
                    xh2[i4 * 2 + 1] = __halves2half2(h2, h3);
                    xl2[i4 * 2]     = __halves2half2(__float2half(o0 - __half2float(h0)),
                                                     __float2half(o1 - __half2float(h1)));
                    xl2[i4 * 2 + 1] = __halves2half2(__float2half(o2 - __half2float(h2)),
                                                     __float2half(o3 - __half2float(h3)));
                }
            }
            __syncthreads();
            if (tid == 0) lnCnt[blockIdx.y] = 0;   // self-reset for next launch/replay
        }
    }
}

// ---------------- FUSED head GEMM + sampling ----------------
// BM=32 rows per CTA, N=128 (cols 0..93 policy, 94 value), K=1024.
__global__ void __launch_bounds__(256, 2)
head_sample_k(const __half* __restrict__ Ahi, const __half* __restrict__ Alo,
              const __half* __restrict__ Bhi, const __half* __restrict__ Blo,
              const float* __restrict__ bias,
              const int* __restrict__ mask, const float* __restrict__ gum,
              float* __restrict__ out, int K)
{
    constexpr uint32_t A_BYTES = 32u * 128u;
    constexpr uint32_t SSTRIDE = A_BYTES + 16384u;

    extern __shared__ char smem_raw[];
    const uint32_t sbase = (smem_to_u32(smem_raw) + 127u) & ~127u;
    const int tid  = threadIdx.x;
    const int wid  = tid >> 5;
    const int lane = tid & 31;
    const int bm   = blockIdx.y * 32;
    const int wm   = (wid >> 2) * 16;
    const int wn   = (wid & 3) * 32;

    const int niter = K >> 5;

    float acc[4][4];
    #pragma unroll
    for (int in = 0; in < 4; in++)
        #pragma unroll
        for (int j = 0; j < 4; j++) acc[in][j] = 0.0f;

    const int ldrow = tid >> 3;
    const int j7    = tid & 7;
    const int halfv = j7 >> 2;
    const int el16  = (j7 & 3) * 8;
    const uint32_t sAoff = SWZ128((uint32_t)(ldrow * 128 + j7 * 16));
    const uint32_t sBoff = A_BYTES + SWZ128((uint32_t)(ldrow * 128 + j7 * 16));
    const __half* Ag = (halfv ? Alo : Ahi) + (size_t)(bm + ldrow) * K + el16;
    const __half* Bg = (halfv ? Blo : Bhi) + (size_t)ldrow * K + el16;
    const size_t gstepA = (size_t)32 * K;

    uint32_t so_ld = 0;
    auto load_stage = [&]() {
        cp16(sbase + so_ld + sAoff, Ag);
        #pragma unroll
        for (int j = 0; j < 4; j++)
            cp16(sbase + so_ld + sBoff + (uint32_t)j * 4096u, Bg + (size_t)j * gstepA);
        Ag += 32; Bg += 32;
        so_ld += SSTRIDE;
        if (so_ld == 3 * SSTRIDE) so_ld = 0;
    };

    const int arow = wm + (lane & 15);
    const int asub = (lane >> 4) << 4;
    const int brow = wn + (lane & 7) + ((lane >> 4) << 3);
    const int bsub = ((lane >> 3) & 1) << 4;
    const uint32_t offA0 = SWZ128((uint32_t)((arow << 7) + asub));
    uint32_t offB[2];
    #pragma unroll
    for (int ib = 0; ib < 2; ib++)
        offB[ib] = A_BYTES + SWZ128((uint32_t)(((brow + ib * 16) << 7) + bsub));

    load_stage();
    asm volatile("cp.async.commit_group;" ::: "memory");
    load_stage();
    asm volatile("cp.async.commit_group;" ::: "memory");

    uint32_t so_cm = 0;
    for (int t = 0; t < niter; t++) {
        asm volatile("cp.async.wait_group 1;" ::: "memory");
        __syncthreads();

        if (t + 2 < niter) load_stage();
        asm volatile("cp.async.commit_group;" ::: "memory");

        const uint32_t sa = sbase + so_cm;
        so_cm += SSTRIDE;
        if (so_cm == 3 * SSTRIDE) so_cm = 0;

        uint32_t aA0 = sa + offA0;
        uint32_t aB[2];
        #pragma unroll
        for (int ib = 0; ib < 2; ib++) aB[ib] = sa + offB[ib];

        #pragma unroll
        for (int ks = 0; ks < 2; ks++) {
            const uint32_t kx = ks ? 32u : 0u;
            uint32_t bh[2][4], bl[2][4];
            #pragma unroll
            for (int ib = 0; ib < 2; ib++) {
                ldm_x4(bh[ib], aB[ib] ^ kx);
                ldm_x4(bl[ib], aB[ib] ^ (kx | 64u));
            }
            {
                uint32_t ah[4];
                ldm_x4(ah, aA0 ^ kx);
                #pragma unroll
                for (int in = 0; in < 4; in++)
                    mma16816(acc[in], ah, &bh[in >> 1][(in & 1) * 2]);
                #pragma unroll
                for (int in = 0; in < 4; in++)
                    mma16816(acc[in], ah, &bl[in >> 1][(in & 1) * 2]);
            }
            {
                uint32_t al[4];
                ldm_x4(al, aA0 ^ (kx | 64u));
                #pragma unroll
                for (int in = 0; in < 4; in++)
                    mma16816(acc[in], al, &bh[in >> 1][(in & 1) * 2]);
            }
        }
    }

    // drain all pending cp.async before smem reuse
    asm volatile("cp.async.wait_group 0;" ::: "memory");
    __syncthreads();

    // stage results to smem: 32 rows x 128 cols, stride 132 floats
    float* scr = (float*)smem_raw;
    {
        int row = wm + (lane >> 2);
        #pragma unroll
        for (int in = 0; in < 4; in++) {
            int col = wn + in * 8 + ((lane & 3) << 1);
            float bx = bias[col], by = bias[col + 1];
            *(float2*)(scr + row * 132 + col)       = make_float2(acc[in][0] + bx, acc[in][1] + by);
            *(float2*)(scr + (row + 8) * 132 + col) = make_float2(acc[in][2] + bx, acc[in][3] + by);
        }
    }
    __syncthreads();

    // sampling: warp wid handles rows wid, wid+8, wid+16, wid+24
    #pragma unroll
    for (int rr = 0; rr < 4; rr++) {
        const int row = wid + rr * 8;
        const int b   = bm + row;
        const float* lr = scr + row * 132;

        for (int a = lane; a < 94; a += 32)
            out[OFF_LOGITS + (long)b * 94 + a] = lr[a];
        if (lane == 0)
            out[OFF_VAL + b] = lr[94];

        int a_prev = -1;
        #pragma unroll
        for (int j = 0; j < 2; j++) {
            int mk[2];
            #pragma unroll
            for (int t = 0; t < 2; t++) {
                int a = lane + 32 * t;
                int m = 0;
                if (a < 47) {
                    m = mask[(long)b * 94 + j * 47 + a];
                    if (j == 1) {
                        if (a_prev >= 1 && a_prev <= 6 && a == a_prev) m = 0;
                        if (a_prev > 26 && a_prev <= 46 && a >= 27)    m = 0;
                        if (a_prev == 0 && a == 0)                     m = 0;
                    }
                }
                mk[t] = m;
            }
            if (j == 1) {
                int ssum = mk[0] + mk[1];
                #pragma unroll
                for (int off = 16; off; off >>= 1)
                    ssum += __shfl_xor_sync(0xffffffffu, ssum, off);
                if (ssum == 0 && a_prev == 0 && lane == 0) mk[0] = 1;
            }

            float lv[2], key[2];
            #pragma unroll
            for (int t = 0; t < 2; t++) {
                int a = lane + 32 * t;
                if (a < 47) {
                    float lg = lr[j * 47 + a];
                    lv[t]  = mk[t] ? lg : NEGV;
                    key[t] = lv[t] + gum[(long)b * 94 + j * 47 + a];
                } else {
                    lv[t]  = -FLT_MAXV;
                    key[t] = -FLT_MAXV;
                }
            }

            float bk = key[0]; int bi = lane;
            if (key[1] > bk) { bk = key[1]; bi = lane + 32; }
            #pragma unroll
            for (int off = 16; off; off >>= 1) {
                float ok = __shfl_xor_sync(0xffffffffu, bk, off);
                int   oi = __shfl_xor_sync(0xffffffffu, bi, off);
                if (ok > bk || (ok == bk && oi < bi)) { bk = ok; bi = oi; }
            }

            float mx = fmaxf(lv[0], lv[1]);
            #pragma unroll
            for (int off = 16; off; off >>= 1)
                mx = fmaxf(mx, __shfl_xor_sync(0xffffffffu, mx, off));
            float es = 0.0f;
            if (lane      < 47) es += expf(lv[0] - mx);
            if (lane + 32 < 47) es += expf(lv[1] - mx);
            #pragma unroll
            for (int off = 16; off; off >>= 1)
                es += __shfl_xor_sync(0xffffffffu, es, off);

            float lsel = __shfl_sync(0xffffffffu, lv[bi >= 32 ? 1 : 0], bi & 31);
            float logp = lsel - mx - logf(es);

            if (lane == 0) {
                out[OFF_LP  + (long)b * 2 + j] = logp;
                out[OFF_ACT + (long)b * 2 + j] = (float)bi;
            }
            a_prev = bi;
        }
    }
}

// ---------------- launcher ----------------
extern "C" void kernel_launch(void* const* d_in, const int* in_sizes, int n_in,
                              void* d_out, int out_size)
{
    const float* obs  = (const float*)d_in[0];
    const int*   am   = (const int*)  d_in[1];
    const float* gum  = (const float*)d_in[2];
    const float* W0   = (const float*)d_in[3];
    const float* b0   = (const float*)d_in[4];
    const float* g0   = (const float*)d_in[5];
    const float* be0  = (const float*)d_in[6];
    const float* W1   = (const float*)d_in[7];
    const float* b1   = (const float*)d_in[8];
    const float* g1   = (const float*)d_in[9];
    const float* be1  = (const float*)d_in[10];
    const float* W2   = (const float*)d_in[11];
    const float* b2   = (const float*)d_in[12];
    const float* g2   = (const float*)d_in[13];
    const float* be2  = (const float*)d_in[14];
    const float* Wp   = (const float*)d_in[15];
    const float* bp   = (const float*)d_in[16];
    const float* Wv   = (const float*)d_in[17];
    const float* bv   = (const float*)d_in[18];
    float* out = (float*)d_out;

    __half *A0h, *A0l, *B0h, *B0l, *B1h, *B1l, *B2h, *B2l, *Bhh, *Bhl, *Xh, *Xl;
    float *bh, *Y;
    int *cnt;
    cudaGetSymbolAddress((void**)&A0h, g_A0h);
    cudaGetSymbolAddress((void**)&A0l, g_A0l);
    cudaGetSymbolAddress((void**)&B0h, g_B0h);
    cudaGetSymbolAddress((void**)&B0l, g_B0l);
    cudaGetSymbolAddress((void**)&B1h, g_B1h);
    cudaGetSymbolAddress((void**)&B1l, g_B1l);
    cudaGetSymbolAddress((void**)&B2h, g_B2h);
    cudaGetSymbolAddress((void**)&B2l, g_B2l);
    cudaGetSymbolAddress((void**)&Bhh, g_Bhh);
    cudaGetSymbolAddress((void**)&Bhl, g_Bhl);
    cudaGetSymbolAddress((void**)&bh,  g_bh);
    cudaGetSymbolAddress((void**)&Y,   g_Y);
    cudaGetSymbolAddress((void**)&Xh,  g_Xh);
    cudaGetSymbolAddress((void**)&Xl,  g_Xl);
    cudaGetSymbolAddress((void**)&cnt, g_cnt);

    const int SMEM_BIG  = 3 * (128 * 128 + 16384) + 128;   // 96 KB + pad (IM=4)
    const int SMEM_HEAD = 3 * (32 * 128 + 16384) + 128;    // 60 KB + pad (head fused)
    cudaFuncSetAttribute(gemm_hmma<4>, cudaFuncAttributeMaxDynamicSharedMemorySize, SMEM_BIG);
    cudaFuncSetAttribute(head_sample_k, cudaFuncAttributeMaxDynamicSharedMemorySize, SMEM_HEAD);

    // --- side streams/events: created ONCE, reused every call (launched work
    //     per call is byte-identical; avoids per-call pool allocation that
    //     would outlive graph teardown) ---
    static cudaStream_t s2 = nullptr, s3 = nullptr;
    static cudaEvent_t evF = nullptr, evW0 = nullptr, evS3 = nullptr;
    if (s2 == nullptr) {
        cudaStreamCreateWithFlags(&s2, cudaStreamNonBlocking);
        cudaStreamCreateWithFlags(&s3, cudaStreamNonBlocking);
        cudaEventCreateWithFlags(&evF,  cudaEventDisableTiming);
        cudaEventCreateWithFlags(&evW0, cudaEventDisableTiming);
        cudaEventCreateWithFlags(&evS3, cudaEventDisableTiming);
    }

    cudaEventRecord(evF, 0);
    cudaStreamWaitEvent(s2, evF, 0);
    cudaStreamWaitEvent(s3, evF, 0);

    // main: obs split (gates L0 via stream order)
    split_obs_k<<<4096, 256>>>(obs);

    // s2: W0 transpose (gates L0)
    transpose_split_k<<<dim3(7168 / 32, 1024 / 32), dim3(32, 8), 0, s2>>>(W0, B0h, B0l, 7150, 7168, 1024);
    cudaEventRecord(evW0, s2);

    // s3: W1/W2/head prep — only needed before L1; overlaps L0 GEMM
    transpose_split_k<<<dim3(1024 / 32, 1024 / 32), dim3(32, 8), 0, s3>>>(W1, B1h, B1l, 1024, 1024, 1024);
    transpose_split_k<<<dim3(1024 / 32, 1024 / 32), dim3(32, 8), 0, s3>>>(W2, B2h, B2l, 1024, 1024, 1024);
    pack_head_k<<<(128 * 1024 + 255) / 256, 256, 0, s3>>>(Wp, bp, Wv, bv);
    cudaEventRecord(evS3, s3);

    cudaStreamWaitEvent(0, evW0, 0);

    dim3 grid0(1024 / 128, 4096 / 128);   // (8, 32)

    // layer 0 (fused LN0 in epilogue)
    gemm_hmma<4><<<grid0, 256, SMEM_BIG>>>(A0h, A0l, B0h, B0l, b0, Y, 1024, 7168,
                                           g0, be0, Xh, Xl, cnt);

    cudaStreamWaitEvent(0, evS3, 0);      // W1/W2/head prep must be done by now

    // layer 1 (fused LN1)
    gemm_hmma<4><<<grid0, 256, SMEM_BIG>>>(Xh, Xl, B1h, B1l, b1, Y, 1024, 1024,
                                           g1, be1, Xh, Xl, cnt);
    // layer 2 (fused LN2)
    gemm_hmma<4><<<grid0, 256, SMEM_BIG>>>(Xh, Xl, B2h, B2l, b2, Y, 1024, 1024,
                                           g2, be2, Xh, Xl, cnt);

    // fused head GEMM + sampling (BM=32 -> 128 CTAs)
    head_sample_k<<<dim3(1, 4096 / 32), 256, SMEM_HEAD>>>(Xh, Xl, Bhh, Bhl, bh, am, gum, out, 1024);
}

// round 13
// speedup vs baseline: 1.1320x; 1.1320x over previous
#include <cuda_runtime.h>
#include <cuda_fp16.h>
#include <cstdint>
#include <math.h>

#define NEGV (-1000000000.0f)
#define FLT_MAXV 3.402823466e38f

// ---------------- output layout ----------------
static const long OFF_LOGITS = 0;
static const long OFF_LP     = 385024;
static const long OFF_ACT    = 393216;
static const long OFF_VAL    = 401408;

#define SWZ128(x) ((x) ^ (((x) >> 3) & 0x70))

__device__ __forceinline__ uint32_t smem_to_u32(const void* p) {
    uint32_t a;
    asm("{ .reg .u64 t; cvta.to.shared.u64 t, %1; cvt.u32.u64 %0, t; }" : "=r"(a) : "l"(p));
    return a;
}
__device__ __forceinline__ void cp16(uint32_t sad, const void* gad) {
    asm volatile("cp.async.cg.shared.global [%0], [%1], 16;" :: "r"(sad), "l"(gad) : "memory");
}
__device__ __forceinline__ void ldm_x4(uint32_t* r, uint32_t addr) {
    asm volatile("ldmatrix.sync.aligned.m8n8.x4.shared.b16 {%0,%1,%2,%3}, [%4];"
                 : "=r"(r[0]), "=r"(r[1]), "=r"(r[2]), "=r"(r[3]) : "r"(addr));
}
__device__ __forceinline__ void mma16816(float* c, const uint32_t* a, const uint32_t* b) {
    asm volatile("mma.sync.aligned.m16n8k16.row.col.f32.f16.f16.f32 "
                 "{%0,%1,%2,%3}, {%4,%5,%6,%7}, {%8,%9}, {%0,%1,%2,%3};"
                 : "+f"(c[0]), "+f"(c[1]), "+f"(c[2]), "+f"(c[3])
                 : "r"(a[0]), "r"(a[1]), "r"(a[2]), "r"(a[3]), "r"(b[0]), "r"(b[1]));
}

// ---------------- scratch (device globals) ----------------
__device__ __half g_A0h[4096L * 7168];
__device__ __half g_A0l[4096L * 7168];
__device__ __half g_B0h[1024L * 7168];
__device__ __half g_B0l[1024L * 7168];
__device__ __half g_B1h[1024L * 1024];
__device__ __half g_B1l[1024L * 1024];
__device__ __half g_B2h[1024L * 1024];
__device__ __half g_B2l[1024L * 1024];
__device__ __half g_Bhh[128L * 1024];
__device__ __half g_Bhl[128L * 1024];
__device__ float  g_bh[128];
__device__ float  g_Y[4096L * 1024];
__device__ __half g_Xh[4096L * 1024];
__device__ __half g_Xl[4096L * 1024];

// ---------------- conversion kernels ----------------
// one block per row; float2 reads, half2 writes, no div/mod
__global__ void split_obs_k(const float* __restrict__ obs) {
    const int r   = blockIdx.x;
    const int tid = threadIdx.x;   // 256
    const float2* src = (const float2*)(obs + (size_t)r * 7150);   // 8B aligned
    __half2* dh = (__half2*)(g_A0h + (size_t)r * 7168);
    __half2* dl = (__half2*)(g_A0l + (size_t)r * 7168);
    #pragma unroll 4
    for (int i = tid; i < 3575; i += 256) {
        float2 v = src[i];
        __half hx = __float2half(v.x);
        __half hy = __float2half(v.y);
        dh[i] = __halves2half2(hx, hy);
        dl[i] = __halves2half2(__float2half(v.x - __half2float(hx)),
                               __float2half(v.y - __half2float(hy)));
    }
    if (tid < 9) {   // pad cols 7150..7167
        __half2 z = __float2half2_rn(0.0f);
        dh[3575 + tid] = z;
        dl[3575 + tid] = z;
    }
}

// W (K x N fp32) -> Bt hi/lo (N x Kpad fp16), transposed + split
__global__ void transpose_split_k(const float* __restrict__ W,
                                  __half* __restrict__ Bh,
                                  __half* __restrict__ Bl,
                                  int K, int Kpad, int N) {
    __shared__ float t[32][33];
    int k0 = blockIdx.x * 32, n0 = blockIdx.y * 32;
    int tx = threadIdx.x, ty = threadIdx.y;   // (32, 8)
    #pragma unroll
    for (int d = 0; d < 4; d++) {
        int k = k0 + ty + d * 8;
        t[ty + d * 8][tx] = (k < K) ? W[(size_t)k * N + n0 + tx] : 0.0f;
    }
    __syncthreads();
    #pragma unroll
    for (int d = 0; d < 4; d++) {
        int n = n0 + ty + d * 8;
        int k = k0 + tx;
        float x = t[tx][ty + d * 8];
        __half h = __float2half(x);
        Bh[(size_t)n * Kpad + k] = h;
        Bl[(size_t)n * Kpad + k] = __float2half(x - __half2float(h));
    }
}

__global__ void pack_head_k(const float* __restrict__ Wp, const float* __restrict__ bp,
                            const float* __restrict__ Wv, const float* __restrict__ bv) {
    int idx = blockIdx.x * blockDim.x + threadIdx.x;
    if (idx < 128 * 1024) {
        int n = idx / 1024;
        int k = idx % 1024;
        float x = 0.0f;
        if (n < 94)       x = Wp[(size_t)k * 94 + n];
        else if (n == 94) x = Wv[k];
        __half h = __float2half(x);
        g_Bhh[idx] = h;
        g_Bhl[idx] = __float2half(x - __half2float(h));
    }
    if (idx < 128) {
        float v = 0.0f;
        if (idx < 94)       v = bp[idx];
        else if (idx == 94) v = bv[0];
        g_bh[idx] = v;
    }
}

// ---------------- HMMA GEMM: C(MxN) = A(MxK) @ Bt(NxK)^T + bias ----------------
// 3-product fp16 split: Ahi@Bhi + Alo@Bhi + Ahi@Blo (all f32-acc; R6 optimum).
// CTA tile (IM*32) x 128, 8 warps, warp tile (IM*16) x 32.
// 3-stage cp.async pipeline, SW128 swizzle, XOR-folded ldmatrix addressing.
template<int IM>
__global__ void __launch_bounds__(256, 2)
gemm_hmma(const __half* __restrict__ Ahi, const __half* __restrict__ Alo,
          const __half* __restrict__ Bhi, const __half* __restrict__ Blo,
          const float* __restrict__ bias, float* __restrict__ C, int N, int K)
{
    constexpr int BM = IM * 32;
    constexpr uint32_t A_BYTES = (uint32_t)BM * 128;
    constexpr uint32_t SSTRIDE = A_BYTES + 16384u;

    extern __shared__ char smem_raw[];
    const uint32_t sbase = (smem_to_u32(smem_raw) + 127u) & ~127u;   // 128B aligned
    const int tid  = threadIdx.x;
    const int wid  = tid >> 5;
    const int lane = tid & 31;
    const int bm   = blockIdx.y * BM;
    const int bn   = blockIdx.x * 128;
    const int wm   = (wid >> 2) * (IM * 16);
    const int wn   = (wid & 3) * 32;

    const int niter = K >> 5;           // 32-wide k-chunks

    float acc[IM][4][4];
    #pragma unroll
    for (int im = 0; im < IM; im++)
        #pragma unroll
        for (int in = 0; in < 4; in++)
            #pragma unroll
            for (int j = 0; j < 4; j++) acc[im][in][j] = 0.0f;

    const int ldrow = tid >> 3;
    const int j7    = tid & 7;
    const int halfv = j7 >> 2;
    const int el16  = (j7 & 3) * 8;
    const uint32_t sAoff = SWZ128((uint32_t)(ldrow * 128 + j7 * 16));
    const uint32_t sBoff = A_BYTES + SWZ128((uint32_t)(ldrow * 128 + j7 * 16));
    const __half* Ag = (halfv ? Alo : Ahi) + (size_t)(bm + ldrow) * K + el16;
    const __half* Bg = (halfv ? Blo : Bhi) + (size_t)(bn + ldrow) * K + el16;
    const size_t gstepA = (size_t)32 * K;

    uint32_t so_ld = 0;
    auto load_stage = [&]() {
        #pragma unroll
        for (int j = 0; j < IM; j++)
            cp16(sbase + so_ld + sAoff + (uint32_t)j * 4096u, Ag + (size_t)j * gstepA);
        #pragma unroll
        for (int j = 0; j < 4; j++)
            cp16(sbase + so_ld + sBoff + (uint32_t)j * 4096u, Bg + (size_t)j * gstepA);
        Ag += 32; Bg += 32;
        so_ld += SSTRIDE;
        if (so_ld == 3 * SSTRIDE) so_ld = 0;
    };

    const int arow = wm + (lane & 15);
    const int asub = (lane >> 4) << 4;
    const int brow = wn + (lane & 7) + ((lane >> 4) << 3);
    const int bsub = ((lane >> 3) & 1) << 4;
    uint32_t offA[IM], offB[2];
    #pragma unroll
    for (int im = 0; im < IM; im++)
        offA[im] = SWZ128((uint32_t)(((arow + im * 16) << 7) + asub));
    #pragma unroll
    for (int ib = 0; ib < 2; ib++)
        offB[ib] = A_BYTES + SWZ128((uint32_t)(((brow + ib * 16) << 7) + bsub));

    load_stage();
    asm volatile("cp.async.commit_group;" ::: "memory");
    load_stage();
    asm volatile("cp.async.commit_group;" ::: "memory");

    uint32_t so_cm = 0;
    for (int t = 0; t < niter; t++) {
        asm volatile("cp.async.wait_group 1;" ::: "memory");
        __syncthreads();

        if (t + 2 < niter) load_stage();
        asm volatile("cp.async.commit_group;" ::: "memory");

        const uint32_t sa = sbase + so_cm;
        so_cm += SSTRIDE;
        if (so_cm == 3 * SSTRIDE) so_cm = 0;

        uint32_t aA[IM], aB[2];
        #pragma unroll
        for (int im = 0; im < IM; im++) aA[im] = sa + offA[im];
        #pragma unroll
        for (int ib = 0; ib < 2; ib++)  aB[ib] = sa + offB[ib];

        #pragma unroll
        for (int ks = 0; ks < 2; ks++) {
            const uint32_t kx = ks ? 32u : 0u;
            uint32_t bh[2][4], bl[2][4];
            #pragma unroll
            for (int ib = 0; ib < 2; ib++) {
                ldm_x4(bh[ib], aB[ib] ^ kx);
                ldm_x4(bl[ib], aB[ib] ^ (kx | 64u));
            }
            {
                uint32_t ah[IM][4];
                #pragma unroll
                for (int im = 0; im < IM; im++)
                    ldm_x4(ah[im], aA[im] ^ kx);
                #pragma unroll
                for (int im = 0; im < IM; im++)
                    #pragma unroll
                    for (int in = 0; in < 4; in++)
                        mma16816(acc[im][in], ah[im], &bh[in >> 1][(in & 1) * 2]);
                #pragma unroll
                for (int im = 0; im < IM; im++)
                    #pragma unroll
                    for (int in = 0; in < 4; in++)
                        mma16816(acc[im][in], ah[im], &bl[in >> 1][(in & 1) * 2]);
            }
            {
                uint32_t al[IM][4];
                #pragma unroll
                for (int im = 0; im < IM; im++)
                    ldm_x4(al[im], aA[im] ^ (kx | 64u));
                #pragma unroll
                for (int im = 0; im < IM; im++)
                    #pragma unroll
                    for (int in = 0; in < 4; in++)
                        mma16816(acc[im][in], al[im], &bh[in >> 1][(in & 1) * 2]);
            }
        }
    }

    // epilogue: bias + direct stores (fragment-native layout)
    #pragma unroll
    for (int in = 0; in < 4; in++) {
        int col = bn + wn + in * 8 + ((lane & 3) << 1);
        float bx = bias[col], by = bias[col + 1];
        #pragma unroll
        for (int im = 0; im < IM; im++) {
            int row = bm + wm + im * 16 + (lane >> 2);
            float2 v0 = { acc[im][in][0] + bx, acc[im][in][1] + by };
            float2 v1 = { acc[im][in][2] + bx, acc[im][in][3] + by };
            *(float2*)(C + (size_t)row * N + col)       = v0;
            *(float2*)(C + (size_t)(row + 8) * N + col) = v1;
        }
    }
}

// ---------------- FUSED head GEMM + sampling ----------------
// BM=32 rows per CTA, N=128 (cols 0..93 policy, 94 value), K=1024.
__global__ void __launch_bounds__(256, 2)
head_sample_k(const __half* __restrict__ Ahi, const __half* __restrict__ Alo,
              const __half* __restrict__ Bhi, const __half* __restrict__ Blo,
              const float* __restrict__ bias,
              const int* __restrict__ mask, const float* __restrict__ gum,
              float* __restrict__ out, int K)
{
    constexpr uint32_t A_BYTES = 32u * 128u;
    constexpr uint32_t SSTRIDE = A_BYTES + 16384u;

    extern __shared__ char smem_raw[];
    const uint32_t sbase = (smem_to_u32(smem_raw) + 127u) & ~127u;
    const int tid  = threadIdx.x;
    const int wid  = tid >> 5;
    const int lane = tid & 31;
    const int bm   = blockIdx.y * 32;
    const int wm   = (wid >> 2) * 16;
    const int wn   = (wid & 3) * 32;

    const int niter = K >> 5;

    float acc[4][4];
    #pragma unroll
    for (int in = 0; in < 4; in++)
        #pragma unroll
        for (int j = 0; j < 4; j++) acc[in][j] = 0.0f;

    const int ldrow = tid >> 3;
    const int j7    = tid & 7;
    const int halfv = j7 >> 2;
    const int el16  = (j7 & 3) * 8;
    const uint32_t sAoff = SWZ128((uint32_t)(ldrow * 128 + j7 * 16));
    const uint32_t sBoff = A_BYTES + SWZ128((uint32_t)(ldrow * 128 + j7 * 16));
    const __half* Ag = (halfv ? Alo : Ahi) + (size_t)(bm + ldrow) * K + el16;
    const __half* Bg = (halfv ? Blo : Bhi) + (size_t)ldrow * K + el16;
    const size_t gstepA = (size_t)32 * K;

    uint32_t so_ld = 0;
    auto load_stage = [&]() {
        cp16(sbase + so_ld + sAoff, Ag);
        #pragma unroll
        for (int j = 0; j < 4; j++)
            cp16(sbase + so_ld + sBoff + (uint32_t)j * 4096u, Bg + (size_t)j * gstepA);
        Ag += 32; Bg += 32;
        so_ld += SSTRIDE;
        if (so_ld == 3 * SSTRIDE) so_ld = 0;
    };

    const int arow = wm + (lane & 15);
    const int asub = (lane >> 4) << 4;
    const int brow = wn + (lane & 7) + ((lane >> 4) << 3);
    const int bsub = ((lane >> 3) & 1) << 4;
    const uint32_t offA0 = SWZ128((uint32_t)((arow << 7) + asub));
    uint32_t offB[2];
    #pragma unroll
    for (int ib = 0; ib < 2; ib++)
        offB[ib] = A_BYTES + SWZ128((uint32_t)(((brow + ib * 16) << 7) + bsub));

    load_stage();
    asm volatile("cp.async.commit_group;" ::: "memory");
    load_stage();
    asm volatile("cp.async.commit_group;" ::: "memory");

    uint32_t so_cm = 0;
    for (int t = 0; t < niter; t++) {
        asm volatile("cp.async.wait_group 1;" ::: "memory");
        __syncthreads();

        if (t + 2 < niter) load_stage();
        asm volatile("cp.async.commit_group;" ::: "memory");

        const uint32_t sa = sbase + so_cm;
        so_cm += SSTRIDE;
        if (so_cm == 3 * SSTRIDE) so_cm = 0;

        uint32_t aA0 = sa + offA0;
        uint32_t aB[2];
        #pragma unroll
        for (int ib = 0; ib < 2; ib++) aB[ib] = sa + offB[ib];

        #pragma unroll
        for (int ks = 0; ks < 2; ks++) {
            const uint32_t kx = ks ? 32u : 0u;
            uint32_t bh[2][4], bl[2][4];
            #pragma unroll
            for (int ib = 0; ib < 2; ib++) {
                ldm_x4(bh[ib], aB[ib] ^ kx);
                ldm_x4(bl[ib], aB[ib] ^ (kx | 64u));
            }
            {
                uint32_t ah[4];
                ldm_x4(ah, aA0 ^ kx);
                #pragma unroll
                for (int in = 0; in < 4; in++)
                    mma16816(acc[in], ah, &bh[in >> 1][(in & 1) * 2]);
                #pragma unroll
                for (int in = 0; in < 4; in++)
                    mma16816(acc[in], ah, &bl[in >> 1][(in & 1) * 2]);
            }
            {
                uint32_t al[4];
                ldm_x4(al, aA0 ^ (kx | 64u));
                #pragma unroll
                for (int in = 0; in < 4; in++)
                    mma16816(acc[in], al, &bh[in >> 1][(in & 1) * 2]);
            }
        }
    }

    // drain all pending cp.async before smem reuse
    asm volatile("cp.async.wait_group 0;" ::: "memory");
    __syncthreads();

    // stage results to smem: 32 rows x 128 cols, stride 132 floats
    float* scr = (float*)smem_raw;
    {
        int row = wm + (lane >> 2);
        #pragma unroll
        for (int in = 0; in < 4; in++) {
            int col = wn + in * 8 + ((lane & 3) << 1);
            float bx = bias[col], by = bias[col + 1];
            *(float2*)(scr + row * 132 + col)       = make_float2(acc[in][0] + bx, acc[in][1] + by);
            *(float2*)(scr + (row + 8) * 132 + col) = make_float2(acc[in][2] + bx, acc[in][3] + by);
        }
    }
    __syncthreads();

    // sampling: warp wid handles rows wid, wid+8, wid+16, wid+24
    #pragma unroll
    for (int rr = 0; rr < 4; rr++) {
        const int row = wid + rr * 8;
        const int b   = bm + row;
        const float* lr = scr + row * 132;

        for (int a = lane; a < 94; a += 32)
            out[OFF_LOGITS + (long)b * 94 + a] = lr[a];
        if (lane == 0)
            out[OFF_VAL + b] = lr[94];

        int a_prev = -1;
        #pragma unroll
        for (int j = 0; j < 2; j++) {
            int mk[2];
            #pragma unroll
            for (int t = 0; t < 2; t++) {
                int a = lane + 32 * t;
                int m = 0;
                if (a < 47) {
                    m = mask[(long)b * 94 + j * 47 + a];
                    if (j == 1) {
                        if (a_prev >= 1 && a_prev <= 6 && a == a_prev) m = 0;
                        if (a_prev > 26 && a_prev <= 46 && a >= 27)    m = 0;
                        if (a_prev == 0 && a == 0)                     m = 0;
                    }
                }
                mk[t] = m;
            }
            if (j == 1) {
                int ssum = mk[0] + mk[1];
                #pragma unroll
                for (int off = 16; off; off >>= 1)
                    ssum += __shfl_xor_sync(0xffffffffu, ssum, off);
                if (ssum == 0 && a_prev == 0 && lane == 0) mk[0] = 1;
            }

            float lv[2], key[2];
            #pragma unroll
            for (int t = 0; t < 2; t++) {
                int a = lane + 32 * t;
                if (a < 47) {
                    float lg = lr[j * 47 + a];
                    lv[t]  = mk[t] ? lg : NEGV;
                    key[t] = lv[t] + gum[(long)b * 94 + j * 47 + a];
                } else {
                    lv[t]  = -FLT_MAXV;
                    key[t] = -FLT_MAXV;
                }
            }

            float bk = key[0]; int bi = lane;
            if (key[1] > bk) { bk = key[1]; bi = lane + 32; }
            #pragma unroll
            for (int off = 16; off; off >>= 1) {
                float ok = __shfl_xor_sync(0xffffffffu, bk, off);
                int   oi = __shfl_xor_sync(0xffffffffu, bi, off);
                if (ok > bk || (ok == bk && oi < bi)) { bk = ok; bi = oi; }
            }

            float mx = fmaxf(lv[0], lv[1]);
            #pragma unroll
            for (int off = 16; off; off >>= 1)
                mx = fmaxf(mx, __shfl_xor_sync(0xffffffffu, mx, off));
            float es = 0.0f;
            if (lane      < 47) es += expf(lv[0] - mx);
            if (lane + 32 < 47) es += expf(lv[1] - mx);
            #pragma unroll
            for (int off = 16; off; off >>= 1)
                es += __shfl_xor_sync(0xffffffffu, es, off);

            float lsel = __shfl_sync(0xffffffffu, lv[bi >= 32 ? 1 : 0], bi & 31);
            float logp = lsel - mx - logf(es);

            if (lane == 0) {
                out[OFF_LP  + (long)b * 2 + j] = logp;
                out[OFF_ACT + (long)b * 2 + j] = (float)bi;
            }
            a_prev = bi;
        }
    }
}

// ---------------- LayerNorm + ReLU + fp16 split: warp-per-row ----------------
// 8 warps/block, 8 rows/block, grid 512. One shuffle reduce, no block syncs.
__global__ void __launch_bounds__(256)
ln_relu_split_k(const float* __restrict__ Y, const float* __restrict__ g,
                const float* __restrict__ be,
                __half* __restrict__ Xh, __half* __restrict__ Xl)
{
    const int wid  = threadIdx.x >> 5;
    const int lane = threadIdx.x & 31;
    const int row  = blockIdx.x * 8 + wid;

    const float4* row4 = (const float4*)(Y + (size_t)row * 1024);
    float4 v[8];
    float s = 0.0f, q = 0.0f;
    #pragma unroll
    for (int j = 0; j < 8; j++) {
        v[j] = row4[lane + j * 32];
        s += v[j].x + v[j].y + v[j].z + v[j].w;
        q += v[j].x * v[j].x + v[j].y * v[j].y + v[j].z * v[j].z + v[j].w * v[j].w;
    }
    #pragma unroll
    for (int o = 16; o; o >>= 1) {
        s += __shfl_xor_sync(0xffffffffu, s, o);
        q += __shfl_xor_sync(0xffffffffu, q, o);
    }
    const float m = s * (1.0f / 1024.0f);
    const float r = rsqrtf(q * (1.0f / 1024.0f) - m * m + 1e-5f);

    __half2* xh2 = (__half2*)(Xh + (size_t)row * 1024);
    __half2* xl2 = (__half2*)(Xl + (size_t)row * 1024);
    #pragma unroll
    for (int j = 0; j < 8; j++) {
        const int i4 = lane + j * 32;
        float4 gv = ((const float4*)g)[i4];
        float4 bv = ((const float4*)be)[i4];
        float o0 = fmaxf(0.0f, (v[j].x - m) * r * gv.x + bv.x);
        float o1 = fmaxf(0.0f, (v[j].y - m) * r * gv.y + bv.y);
        float o2 = fmaxf(0.0f, (v[j].z - m) * r * gv.z + bv.z);
        float o3 = fmaxf(0.0f, (v[j].w - m) * r * gv.w + bv.w);
        __half h0 = __float2half(o0), h1 = __float2half(o1);
        __half h2 = __float2half(o2), h3 = __float2half(o3);
        xh2[i4 * 2]     = __halves2half2(h0, h1);
        xh2[i4 * 2 + 1] = __halves2half2(h2, h3);
        xl2[i4 * 2]     = __halves2half2(__float2half(o0 - __half2float(h0)),
                                         __float2half(o1 - __half2float(h1)));
        xl2[i4 * 2 + 1] = __halves2half2(__float2half(o2 - __half2float(h2)),
                                         __float2half(o3 - __half2float(h3)));
    }
}

// ---------------- launcher ----------------
extern "C" void kernel_launch(void* const* d_in, const int* in_sizes, int n_in,
                              void* d_out, int out_size)
{
    const float* obs  = (const float*)d_in[0];
    const int*   am   = (const int*)  d_in[1];
    const float* gum  = (const float*)d_in[2];
    const float* W0   = (const float*)d_in[3];
    const float* b0   = (const float*)d_in[4];
    const float* g0   = (const float*)d_in[5];
    const float* be0  = (const float*)d_in[6];
    const float* W1   = (const float*)d_in[7];
    const float* b1   = (const float*)d_in[8];
    const float* g1   = (const float*)d_in[9];
    const float* be1  = (const float*)d_in[10];
    const float* W2   = (const float*)d_in[11];
    const float* b2   = (const float*)d_in[12];
    const float* g2   = (const float*)d_in[13];
    const float* be2  = (const float*)d_in[14];
    const float* Wp   = (const float*)d_in[15];
    const float* bp   = (const float*)d_in[16];
    const float* Wv   = (const float*)d_in[17];
    const float* bv   = (const float*)d_in[18];
    float* out = (float*)d_out;

    __half *A0h, *A0l, *B0h, *B0l, *B1h, *B1l, *B2h, *B2l, *Bhh, *Bhl, *Xh, *Xl;
    float *bh, *Y;
    cudaGetSymbolAddress((void**)&A0h, g_A0h);
    cudaGetSymbolAddress((void**)&A0l, g_A0l);
    cudaGetSymbolAddress((void**)&B0h, g_B0h);
    cudaGetSymbolAddress((void**)&B0l, g_B0l);
    cudaGetSymbolAddress((void**)&B1h, g_B1h);
    cudaGetSymbolAddress((void**)&B1l, g_B1l);
    cudaGetSymbolAddress((void**)&B2h, g_B2h);
    cudaGetSymbolAddress((void**)&B2l, g_B2l);
    cudaGetSymbolAddress((void**)&Bhh, g_Bhh);
    cudaGetSymbolAddress((void**)&Bhl, g_Bhl);
    cudaGetSymbolAddress((void**)&bh,  g_bh);
    cudaGetSymbolAddress((void**)&Y,   g_Y);
    cudaGetSymbolAddress((void**)&Xh,  g_Xh);
    cudaGetSymbolAddress((void**)&Xl,  g_Xl);

    const int SMEM_BIG  = 3 * (128 * 128 + 16384) + 128;   // 96 KB + pad (IM=4)
    const int SMEM_HEAD = 3 * (32 * 128 + 16384) + 128;    // 60 KB + pad (head fused)
    cudaFuncSetAttribute(gemm_hmma<4>, cudaFuncAttributeMaxDynamicSharedMemorySize, SMEM_BIG);
    cudaFuncSetAttribute(head_sample_k, cudaFuncAttributeMaxDynamicSharedMemorySize, SMEM_HEAD);

    // --- side streams/events: created ONCE, reused every call (launched work
    //     per call is byte-identical; avoids per-call pool allocation that
    //     would outlive graph teardown) ---
    static cudaStream_t s2 = nullptr, s3 = nullptr;
    static cudaEvent_t evF = nullptr, evW0 = nullptr, evS3 = nullptr;
    if (s2 == nullptr) {
        cudaStreamCreateWithFlags(&s2, cudaStreamNonBlocking);
        cudaStreamCreateWithFlags(&s3, cudaStreamNonBlocking);
        cudaEventCreateWithFlags(&evF,  cudaEventDisableTiming);
        cudaEventCreateWithFlags(&evW0, cudaEventDisableTiming);
        cudaEventCreateWithFlags(&evS3, cudaEventDisableTiming);
    }

    cudaEventRecord(evF, 0);
    cudaStreamWaitEvent(s2, evF, 0);
    cudaStreamWaitEvent(s3, evF, 0);

    // main: obs split (gates L0 via stream order)
    split_obs_k<<<4096, 256>>>(obs);

    // s2: W0 transpose (gates L0)
    transpose_split_k<<<dim3(7168 / 32, 1024 / 32), dim3(32, 8), 0, s2>>>(W0, B0h, B0l, 7150, 7168, 1024);
    cudaEventRecord(evW0, s2);

    // s3: W1/W2/head prep — only needed before L1; overlaps L0 GEMM
    transpose_split_k<<<dim3(1024 / 32, 1024 / 32), dim3(32, 8), 0, s3>>>(W1, B1h, B1l, 1024, 1024, 1024);
    transpose_split_k<<<dim3(1024 / 32, 1024 / 32), dim3(32, 8), 0, s3>>>(W2, B2h, B2l, 1024, 1024, 1024);
    pack_head_k<<<(128 * 1024 + 255) / 256, 256, 0, s3>>>(Wp, bp, Wv, bv);
    cudaEventRecord(evS3, s3);

    cudaStreamWaitEvent(0, evW0, 0);

    dim3 grid0(1024 / 128, 4096 / 128);   // (8, 32)

    // layer 0
    gemm_hmma<4><<<grid0, 256, SMEM_BIG>>>(A0h, A0l, B0h, B0l, b0, Y, 1024, 7168);
    ln_relu_split_k<<<512, 256>>>(Y, g0, be0, Xh, Xl);

    cudaStreamWaitEvent(0, evS3, 0);      // W1/W2/head prep must be done by now

    // layer 1
    gemm_hmma<4><<<grid0, 256, SMEM_BIG>>>(Xh, Xl, B1h, B1l, b1, Y, 1024, 1024);
    ln_relu_split_k<<<512, 256>>>(Y, g1, be1, Xh, Xl);
    // layer 2
    gemm_hmma<4><<<grid0, 256, SMEM_BIG>>>(Xh, Xl, B2h, B2l, b2, Y, 1024, 1024);
    ln_relu_split_k<<<512, 256>>>(Y, g2, be2, Xh, Xl);

    // fused head GEMM + sampling (BM=32 -> 128 CTAs)
    head_sample_k<<<dim3(1, 4096 / 32), 256, SMEM_HEAD>>>(Xh, Xl, Bhh, Bhl, bh, am, gum, out, 1024);
}

// round 14
// speedup vs baseline: 1.2255x; 1.0826x over previous
#include <cuda_runtime.h>
#include <cuda_fp16.h>
#include <cstdint>
#include <math.h>

#define NEGV (-1000000000.0f)
#define FLT_MAXV 3.402823466e38f

// ---------------- output layout ----------------
static const long OFF_LOGITS = 0;
static const long OFF_LP     = 385024;
static const long OFF_ACT    = 393216;
static const long OFF_VAL    = 401408;

#define SWZ128(x) ((x) ^ (((x) >> 3) & 0x70))

__device__ __forceinline__ uint32_t smem_to_u32(const void* p) {
    uint32_t a;
    asm("{ .reg .u64 t; cvta.to.shared.u64 t, %1; cvt.u32.u64 %0, t; }" : "=r"(a) : "l"(p));
    return a;
}
__device__ __forceinline__ void cp16(uint32_t sad, const void* gad) {
    asm volatile("cp.async.cg.shared.global [%0], [%1], 16;" :: "r"(sad), "l"(gad) : "memory");
}
__device__ __forceinline__ void ldm_x4(uint32_t* r, uint32_t addr) {
    asm volatile("ldmatrix.sync.aligned.m8n8.x4.shared.b16 {%0,%1,%2,%3}, [%4];"
                 : "=r"(r[0]), "=r"(r[1]), "=r"(r[2]), "=r"(r[3]) : "r"(addr));
}
__device__ __forceinline__ void mma16816(float* c, const uint32_t* a, const uint32_t* b) {
    asm volatile("mma.sync.aligned.m16n8k16.row.col.f32.f16.f16.f32 "
                 "{%0,%1,%2,%3}, {%4,%5,%6,%7}, {%8,%9}, {%0,%1,%2,%3};"
                 : "+f"(c[0]), "+f"(c[1]), "+f"(c[2]), "+f"(c[3])
                 : "r"(a[0]), "r"(a[1]), "r"(a[2]), "r"(a[3]), "r"(b[0]), "r"(b[1]));
}

// ---------------- scratch (device globals) ----------------
__device__ __half g_A0h[4096L * 7168];
__device__ __half g_A0l[4096L * 7168];
__device__ __half g_B0h[1024L * 7168];
__device__ __half g_B0l[1024L * 7168];
__device__ __half g_B1h[1024L * 1024];
__device__ __half g_B1l[1024L * 1024];
__device__ __half g_B2h[1024L * 1024];
__device__ __half g_B2l[1024L * 1024];
__device__ __half g_Bhh[128L * 1024];
__device__ __half g_Bhl[128L * 1024];
__device__ float  g_bh[128];
__device__ float  g_Y[4096L * 1024];
__device__ float  g_Ys[4L * 4096 * 1024];   // split-K partial sums (L0)
__device__ __half g_Xh[4096L * 1024];
__device__ __half g_Xl[4096L * 1024];

// ---------------- conversion kernels ----------------
// one block per row; float2 reads, half2 writes, no div/mod
__global__ void split_obs_k(const float* __restrict__ obs) {
    const int r   = blockIdx.x;
    const int tid = threadIdx.x;   // 256
    const float2* src = (const float2*)(obs + (size_t)r * 7150);   // 8B aligned
    __half2* dh = (__half2*)(g_A0h + (size_t)r * 7168);
    __half2* dl = (__half2*)(g_A0l + (size_t)r * 7168);
    #pragma unroll 4
    for (int i = tid; i < 3575; i += 256) {
        float2 v = src[i];
        __half hx = __float2half(v.x);
        __half hy = __float2half(v.y);
        dh[i] = __halves2half2(hx, hy);
        dl[i] = __halves2half2(__float2half(v.x - __half2float(hx)),
                               __float2half(v.y - __half2float(hy)));
    }
    if (tid < 9) {   // pad cols 7150..7167
        __half2 z = __float2half2_rn(0.0f);
        dh[3575 + tid] = z;
        dl[3575 + tid] = z;
    }
}

// W (K x N fp32) -> Bt hi/lo (N x Kpad fp16), transposed + split
__global__ void transpose_split_k(const float* __restrict__ W,
                                  __half* __restrict__ Bh,
                                  __half* __restrict__ Bl,
                                  int K, int Kpad, int N) {
    __shared__ float t[32][33];
    int k0 = blockIdx.x * 32, n0 = blockIdx.y * 32;
    int tx = threadIdx.x, ty = threadIdx.y;   // (32, 8)
    #pragma unroll
    for (int d = 0; d < 4; d++) {
        int k = k0 + ty + d * 8;
        t[ty + d * 8][tx] = (k < K) ? W[(size_t)k * N + n0 + tx] : 0.0f;
    }
    __syncthreads();
    #pragma unroll
    for (int d = 0; d < 4; d++) {
        int n = n0 + ty + d * 8;
        int k = k0 + tx;
        float x = t[tx][ty + d * 8];
        __half h = __float2half(x);
        Bh[(size_t)n * Kpad + k] = h;
        Bl[(size_t)n * Kpad + k] = __float2half(x - __half2float(h));
    }
}

__global__ void pack_head_k(const float* __restrict__ Wp, const float* __restrict__ bp,
                            const float* __restrict__ Wv, const float* __restrict__ bv) {
    int idx = blockIdx.x * blockDim.x + threadIdx.x;
    if (idx < 128 * 1024) {
        int n = idx / 1024;
        int k = idx % 1024;
        float x = 0.0f;
        if (n < 94)       x = Wp[(size_t)k * 94 + n];
        else if (n == 94) x = Wv[k];
        __half h = __float2half(x);
        g_Bhh[idx] = h;
        g_Bhl[idx] = __float2half(x - __half2float(h));
    }
    if (idx < 128) {
        float v = 0.0f;
        if (idx < 94)       v = bp[idx];
        else if (idx == 94) v = bv[0];
        g_bh[idx] = v;
    }
}

// ---------------- HMMA GEMM: C = A(MxK) @ Bt(NxK)^T (+ bias) ----------------
// 3-product fp16 split: Ahi@Bhi + Alo@Bhi + Ahi@Blo (all f32-acc; R6 optimum).
// CTA tile (IM*32) x 128, 8 warps; 3-stage cp.async, SW128, XOR-folded ldmatrix.
// Split-K: blockIdx.z processes nkcSplit k-chunks starting at z*nkcSplit and
// writes to partial buffer z (stride M*N); bias applied only when gridDim.z==1.
template<int IM>
__global__ void __launch_bounds__(256, 2)
gemm_hmma(const __half* __restrict__ Ahi, const __half* __restrict__ Alo,
          const __half* __restrict__ Bhi, const __half* __restrict__ Blo,
          const float* __restrict__ bias, float* __restrict__ C, int N, int K,
          int nkcSplit)
{
    constexpr int BM = IM * 32;
    constexpr uint32_t A_BYTES = (uint32_t)BM * 128;
    constexpr uint32_t SSTRIDE = A_BYTES + 16384u;

    extern __shared__ char smem_raw[];
    const uint32_t sbase = (smem_to_u32(smem_raw) + 127u) & ~127u;   // 128B aligned
    const int tid  = threadIdx.x;
    const int wid  = tid >> 5;
    const int lane = tid & 31;
    const int bm   = blockIdx.y * BM;
    const int bn   = blockIdx.x * 128;
    const int wm   = (wid >> 2) * (IM * 16);
    const int wn   = (wid & 3) * 32;

    const int niter = nkcSplit;
    const int kc0   = blockIdx.z * nkcSplit;
    const bool doBias = (gridDim.z == 1);
    if (!doBias)
        C += (size_t)blockIdx.z * (size_t)(gridDim.y * BM) * N;

    float acc[IM][4][4];
    #pragma unroll
    for (int im = 0; im < IM; im++)
        #pragma unroll
        for (int in = 0; in < 4; in++)
            #pragma unroll
            for (int j = 0; j < 4; j++) acc[im][in][j] = 0.0f;

    const int ldrow = tid >> 3;
    const int j7    = tid & 7;
    const int halfv = j7 >> 2;
    const int el16  = (j7 & 3) * 8;
    const uint32_t sAoff = SWZ128((uint32_t)(ldrow * 128 + j7 * 16));
    const uint32_t sBoff = A_BYTES + SWZ128((uint32_t)(ldrow * 128 + j7 * 16));
    const __half* Ag = (halfv ? Alo : Ahi) + (size_t)(bm + ldrow) * K + el16 + ((size_t)kc0 << 5);
    const __half* Bg = (halfv ? Blo : Bhi) + (size_t)(bn + ldrow) * K + el16 + ((size_t)kc0 << 5);
    const size_t gstepA = (size_t)32 * K;

    uint32_t so_ld = 0;
    auto load_stage = [&]() {
        #pragma unroll
        for (int j = 0; j < IM; j++)
            cp16(sbase + so_ld + sAoff + (uint32_t)j * 4096u, Ag + (size_t)j * gstepA);
        #pragma unroll
        for (int j = 0; j < 4; j++)
            cp16(sbase + so_ld + sBoff + (uint32_t)j * 4096u, Bg + (size_t)j * gstepA);
        Ag += 32; Bg += 32;
        so_ld += SSTRIDE;
        if (so_ld == 3 * SSTRIDE) so_ld = 0;
    };

    const int arow = wm + (lane & 15);
    const int asub = (lane >> 4) << 4;
    const int brow = wn + (lane & 7) + ((lane >> 4) << 3);
    const int bsub = ((lane >> 3) & 1) << 4;
    uint32_t offA[IM], offB[2];
    #pragma unroll
    for (int im = 0; im < IM; im++)
        offA[im] = SWZ128((uint32_t)(((arow + im * 16) << 7) + asub));
    #pragma unroll
    for (int ib = 0; ib < 2; ib++)
        offB[ib] = A_BYTES + SWZ128((uint32_t)(((brow + ib * 16) << 7) + bsub));

    load_stage();
    asm volatile("cp.async.commit_group;" ::: "memory");
    load_stage();
    asm volatile("cp.async.commit_group;" ::: "memory");

    uint32_t so_cm = 0;
    for (int t = 0; t < niter; t++) {
        asm volatile("cp.async.wait_group 1;" ::: "memory");
        __syncthreads();

        if (t + 2 < niter) load_stage();
        asm volatile("cp.async.commit_group;" ::: "memory");

        const uint32_t sa = sbase + so_cm;
        so_cm += SSTRIDE;
        if (so_cm == 3 * SSTRIDE) so_cm = 0;

        uint32_t aA[IM], aB[2];
        #pragma unroll
        for (int im = 0; im < IM; im++) aA[im] = sa + offA[im];
        #pragma unroll
        for (int ib = 0; ib < 2; ib++)  aB[ib] = sa + offB[ib];

        #pragma unroll
        for (int ks = 0; ks < 2; ks++) {
            const uint32_t kx = ks ? 32u : 0u;
            uint32_t bh[2][4], bl[2][4];
            #pragma unroll
            for (int ib = 0; ib < 2; ib++) {
                ldm_x4(bh[ib], aB[ib] ^ kx);
                ldm_x4(bl[ib], aB[ib] ^ (kx | 64u));
            }
            {
                uint32_t ah[IM][4];
                #pragma unroll
                for (int im = 0; im < IM; im++)
                    ldm_x4(ah[im], aA[im] ^ kx);
                #pragma unroll
                for (int im = 0; im < IM; im++)
                    #pragma unroll
                    for (int in = 0; in < 4; in++)
                        mma16816(acc[im][in], ah[im], &bh[in >> 1][(in & 1) * 2]);
                #pragma unroll
                for (int im = 0; im < IM; im++)
                    #pragma unroll
                    for (int in = 0; in < 4; in++)
                        mma16816(acc[im][in], ah[im], &bl[in >> 1][(in & 1) * 2]);
            }
            {
                uint32_t al[IM][4];
                #pragma unroll
                for (int im = 0; im < IM; im++)
                    ldm_x4(al[im], aA[im] ^ (kx | 64u));
                #pragma unroll
                for (int im = 0; im < IM; im++)
                    #pragma unroll
                    for (int in = 0; in < 4; in++)
                        mma16816(acc[im][in], al[im], &bh[in >> 1][(in & 1) * 2]);
            }
        }
    }

    // epilogue: (optional bias) + direct stores (fragment-native layout)
    #pragma unroll
    for (int in = 0; in < 4; in++) {
        int col = bn + wn + in * 8 + ((lane & 3) << 1);
        float bx = doBias ? bias[col]     : 0.0f;
        float by = doBias ? bias[col + 1] : 0.0f;
        #pragma unroll
        for (int im = 0; im < IM; im++) {
            int row = bm + wm + im * 16 + (lane >> 2);
            float2 v0 = { acc[im][in][0] + bx, acc[im][in][1] + by };
            float2 v1 = { acc[im][in][2] + bx, acc[im][in][3] + by };
            *(float2*)(C + (size_t)row * N + col)       = v0;
            *(float2*)(C + (size_t)(row + 8) * N + col) = v1;
        }
    }
}

// ---------------- FUSED head GEMM + sampling ----------------
// BM=32 rows per CTA, N=128 (cols 0..93 policy, 94 value), K=1024.
__global__ void __launch_bounds__(256, 2)
head_sample_k(const __half* __restrict__ Ahi, const __half* __restrict__ Alo,
              const __half* __restrict__ Bhi, const __half* __restrict__ Blo,
              const float* __restrict__ bias,
              const int* __restrict__ mask, const float* __restrict__ gum,
              float* __restrict__ out, int K)
{
    constexpr uint32_t A_BYTES = 32u * 128u;
    constexpr uint32_t SSTRIDE = A_BYTES + 16384u;

    extern __shared__ char smem_raw[];
    const uint32_t sbase = (smem_to_u32(smem_raw) + 127u) & ~127u;
    const int tid  = threadIdx.x;
    const int wid  = tid >> 5;
    const int lane = tid & 31;
    const int bm   = blockIdx.y * 32;
    const int wm   = (wid >> 2) * 16;
    const int wn   = (wid & 3) * 32;

    const int niter = K >> 5;

    float acc[4][4];
    #pragma unroll
    for (int in = 0; in < 4; in++)
        #pragma unroll
        for (int j = 0; j < 4; j++) acc[in][j] = 0.0f;

    const int ldrow = tid >> 3;
    const int j7    = tid & 7;
    const int halfv = j7 >> 2;
    const int el16  = (j7 & 3) * 8;
    const uint32_t sAoff = SWZ128((uint32_t)(ldrow * 128 + j7 * 16));
    const uint32_t sBoff = A_BYTES + SWZ128((uint32_t)(ldrow * 128 + j7 * 16));
    const __half* Ag = (halfv ? Alo : Ahi) + (size_t)(bm + ldrow) * K + el16;
    const __half* Bg = (halfv ? Blo : Bhi) + (size_t)ldrow * K + el16;
    const size_t gstepA = (size_t)32 * K;

    uint32_t so_ld = 0;
    auto load_stage = [&]() {
        cp16(sbase + so_ld + sAoff, Ag);
        #pragma unroll
        for (int j = 0; j < 4; j++)
            cp16(sbase + so_ld + sBoff + (uint32_t)j * 4096u, Bg + (size_t)j * gstepA);
        Ag += 32; Bg += 32;
        so_ld += SSTRIDE;
        if (so_ld == 3 * SSTRIDE) so_ld = 0;
    };

    const int arow = wm + (lane & 15);
    const int asub = (lane >> 4) << 4;
    const int brow = wn + (lane & 7) + ((lane >> 4) << 3);
    const int bsub = ((lane >> 3) & 1) << 4;
    const uint32_t offA0 = SWZ128((uint32_t)((arow << 7) + asub));
    uint32_t offB[2];
    #pragma unroll
    for (int ib = 0; ib < 2; ib++)
        offB[ib] = A_BYTES + SWZ128((uint32_t)(((brow + ib * 16) << 7) + bsub));

    load_stage();
    asm volatile("cp.async.commit_group;" ::: "memory");
    load_stage();
    asm volatile("cp.async.commit_group;" ::: "memory");

    uint32_t so_cm = 0;
    for (int t = 0; t < niter; t++) {
        asm volatile("cp.async.wait_group 1;" ::: "memory");
        __syncthreads();

        if (t + 2 < niter) load_stage();
        asm volatile("cp.async.commit_group;" ::: "memory");

        const uint32_t sa = sbase + so_cm;
        so_cm += SSTRIDE;
        if (so_cm == 3 * SSTRIDE) so_cm = 0;

        uint32_t aA0 = sa + offA0;
        uint32_t aB[2];
        #pragma unroll
        for (int ib = 0; ib < 2; ib++) aB[ib] = sa + offB[ib];

        #pragma unroll
        for (int ks = 0; ks < 2; ks++) {
            const uint32_t kx = ks ? 32u : 0u;
            uint32_t bh[2][4], bl[2][4];
            #pragma unroll
            for (int ib = 0; ib < 2; ib++) {
                ldm_x4(bh[ib], aB[ib] ^ kx);
                ldm_x4(bl[ib], aB[ib] ^ (kx | 64u));
            }
            {
                uint32_t ah[4];
                ldm_x4(ah, aA0 ^ kx);
                #pragma unroll
                for (int in = 0; in < 4; in++)
                    mma16816(acc[in], ah, &bh[in >> 1][(in & 1) * 2]);
                #pragma unroll
                for (int in = 0; in < 4; in++)
                    mma16816(acc[in], ah, &bl[in >> 1][(in & 1) * 2]);
            }
            {
                uint32_t al[4];
                ldm_x4(al, aA0 ^ (kx | 64u));
                #pragma unroll
                for (int in = 0; in < 4; in++)
                    mma16816(acc[in], al, &bh[in >> 1][(in & 1) * 2]);
            }
        }
    }

    // drain all pending cp.async before smem reuse
    asm volatile("cp.async.wait_group 0;" ::: "memory");
    __syncthreads();

    // stage results to smem: 32 rows x 128 cols, stride 132 floats
    float* scr = (float*)smem_raw;
    {
        int row = wm + (lane >> 2);
        #pragma unroll
        for (int in = 0; in < 4; in++) {
            int col = wn + in * 8 + ((lane & 3) << 1);
            float bx = bias[col], by = bias[col + 1];
            *(float2*)(scr + row * 132 + col)       = make_float2(acc[in][0] + bx, acc[in][1] + by);
            *(float2*)(scr + (row + 8) * 132 + col) = make_float2(acc[in][2] + bx, acc[in][3] + by);
        }
    }
    __syncthreads();

    // sampling: warp wid handles rows wid, wid+8, wid+16, wid+24
    #pragma unroll
    for (int rr = 0; rr < 4; rr++) {
        const int row = wid + rr * 8;
        const int b   = bm + row;
        const float* lr = scr + row * 132;

        for (int a = lane; a < 94; a += 32)
            out[OFF_LOGITS + (long)b * 94 + a] = lr[a];
        if (lane == 0)
            out[OFF_VAL + b] = lr[94];

        int a_prev = -1;
        #pragma unroll
        for (int j = 0; j < 2; j++) {
            int mk[2];
            #pragma unroll
            for (int t = 0; t < 2; t++) {
                int a = lane + 32 * t;
                int m = 0;
                if (a < 47) {
                    m = mask[(long)b * 94 + j * 47 + a];
                    if (j == 1) {
                        if (a_prev >= 1 && a_prev <= 6 && a == a_prev) m = 0;
                        if (a_prev > 26 && a_prev <= 46 && a >= 27)    m = 0;
                        if (a_prev == 0 && a == 0)                     m = 0;
                    }
                }
                mk[t] = m;
            }
            if (j == 1) {
                int ssum = mk[0] + mk[1];
                #pragma unroll
                for (int off = 16; off; off >>= 1)
                    ssum += __shfl_xor_sync(0xffffffffu, ssum, off);
                if (ssum == 0 && a_prev == 0 && lane == 0) mk[0] = 1;
            }

            float lv[2], key[2];
            #pragma unroll
            for (int t = 0; t < 2; t++) {
                int a = lane + 32 * t;
                if (a < 47) {
                    float lg = lr[j * 47 + a];
                    lv[t]  = mk[t] ? lg : NEGV;
                    key[t] = lv[t] + gum[(long)b * 94 + j * 47 + a];
                } else {
                    lv[t]  = -FLT_MAXV;
                    key[t] = -FLT_MAXV;
                }
            }

            float bk = key[0]; int bi = lane;
            if (key[1] > bk) { bk = key[1]; bi = lane + 32; }
            #pragma unroll
            for (int off = 16; off; off >>= 1) {
                float ok = __shfl_xor_sync(0xffffffffu, bk, off);
                int   oi = __shfl_xor_sync(0xffffffffu, bi, off);
                if (ok > bk || (ok == bk && oi < bi)) { bk = ok; bi = oi; }
            }

            float mx = fmaxf(lv[0], lv[1]);
            #pragma unroll
            for (int off = 16; off; off >>= 1)
                mx = fmaxf(mx, __shfl_xor_sync(0xffffffffu, mx, off));
            float es = 0.0f;
            if (lane      < 47) es += expf(lv[0] - mx);
            if (lane + 32 < 47) es += expf(lv[1] - mx);
            #pragma unroll
            for (int off = 16; off; off >>= 1)
                es += __shfl_xor_sync(0xffffffffu, es, off);

            float lsel = __shfl_sync(0xffffffffu, lv[bi >= 32 ? 1 : 0], bi & 31);
            float logp = lsel - mx - logf(es);

            if (lane == 0) {
                out[OFF_LP  + (long)b * 2 + j] = logp;
                out[OFF_ACT + (long)b * 2 + j] = (float)bi;
            }
            a_prev = bi;
        }
    }
}

// ---------------- LayerNorm + ReLU + fp16 split: warp-per-row ----------------
__global__ void __launch_bounds__(256)
ln_relu_split_k(const float* __restrict__ Y, const float* __restrict__ g,
                const float* __restrict__ be,
                __half* __restrict__ Xh, __half* __restrict__ Xl)
{
    const int wid  = threadIdx.x >> 5;
    const int lane = threadIdx.x & 31;
    const int row  = blockIdx.x * 8 + wid;

    const float4* row4 = (const float4*)(Y + (size_t)row * 1024);
    float4 v[8];
    float s = 0.0f, q = 0.0f;
    #pragma unroll
    for (int j = 0; j < 8; j++) {
        v[j] = row4[lane + j * 32];
        s += v[j].x + v[j].y + v[j].z + v[j].w;
        q += v[j].x * v[j].x + v[j].y * v[j].y + v[j].z * v[j].z + v[j].w * v[j].w;
    }
    #pragma unroll
    for (int o = 16; o; o >>= 1) {
        s += __shfl_xor_sync(0xffffffffu, s, o);
        q += __shfl_xor_sync(0xffffffffu, q, o);
    }
    const float m = s * (1.0f / 1024.0f);
    const float r = rsqrtf(q * (1.0f / 1024.0f) - m * m + 1e-5f);

    __half2* xh2 = (__half2*)(Xh + (size_t)row * 1024);
    __half2* xl2 = (__half2*)(Xl + (size_t)row * 1024);
    #pragma unroll
    for (int j = 0; j < 8; j++) {
        const int i4 = lane + j * 32;
        float4 gv = ((const float4*)g)[i4];
        float4 bv = ((const float4*)be)[i4];
        float o0 = fmaxf(0.0f, (v[j].x - m) * r * gv.x + bv.x);
        float o1 = fmaxf(0.0f, (v[j].y - m) * r * gv.y + bv.y);
        float o2 = fmaxf(0.0f, (v[j].z - m) * r * gv.z + bv.z);
        float o3 = fmaxf(0.0f, (v[j].w - m) * r * gv.w + bv.w);
        __half h0 = __float2half(o0), h1 = __float2half(o1);
        __half h2 = __float2half(o2), h3 = __float2half(o3);
        xh2[i4 * 2]     = __halves2half2(h0, h1);
        xh2[i4 * 2 + 1] = __halves2half2(h2, h3);
        xl2[i4 * 2]     = __halves2half2(__float2half(o0 - __half2float(h0)),
                                         __float2half(o1 - __half2float(h1)));
        xl2[i4 * 2 + 1] = __halves2half2(__float2half(o2 - __half2float(h2)),
                                         __float2half(o3 - __half2float(h3)));
    }
}

// ---------------- LN variant: sum 4 split-K partials + bias, then LN ----------
__global__ void __launch_bounds__(256)
ln4_relu_split_k(const float* __restrict__ Ys, const float* __restrict__ bias,
                 const float* __restrict__ g, const float* __restrict__ be,
                 __half* __restrict__ Xh, __half* __restrict__ Xl)
{
    const int wid  = threadIdx.x >> 5;
    const int lane = threadIdx.x & 31;
    const int row  = blockIdx.x * 8 + wid;
    const size_t PART = 4096L * 1024;

    const float4* r0 = (const float4*)(Ys + (size_t)row * 1024);
    const float4* r1 = (const float4*)(Ys + PART     + (size_t)row * 1024);
    const float4* r2 = (const float4*)(Ys + PART * 2 + (size_t)row * 1024);
    const float4* r3 = (const float4*)(Ys + PART * 3 + (size_t)row * 1024);

    float4 v[8];
    float s = 0.0f, q = 0.0f;
    #pragma unroll
    for (int j = 0; j < 8; j++) {
        const int i4 = lane + j * 32;
        float4 a = r0[i4], b = r1[i4], c = r2[i4], d = r3[i4];
        float4 bs = ((const float4*)bias)[i4];
        v[j].x = a.x + b.x + c.x + d.x + bs.x;
        v[j].y = a.y + b.y + c.y + d.y + bs.y;
        v[j].z = a.z + b.z + c.z + d.z + bs.z;
        v[j].w = a.w + b.w + c.w + d.w + bs.w;
        s += v[j].x + v[j].y + v[j].z + v[j].w;
        q += v[j].x * v[j].x + v[j].y * v[j].y + v[j].z * v[j].z + v[j].w * v[j].w;
    }
    #pragma unroll
    for (int o = 16; o; o >>= 1) {
        s += __shfl_xor_sync(0xffffffffu, s, o);
        q += __shfl_xor_sync(0xffffffffu, q, o);
    }
    const float m = s * (1.0f / 1024.0f);
    const float r = rsqrtf(q * (1.0f / 1024.0f) - m * m + 1e-5f);

    __half2* xh2 = (__half2*)(Xh + (size_t)row * 1024);
    __half2* xl2 = (__half2*)(Xl + (size_t)row * 1024);
    #pragma unroll
    for (int j = 0; j < 8; j++) {
        const int i4 = lane + j * 32;
        float4 gv = ((const float4*)g)[i4];
        float4 bv = ((const float4*)be)[i4];
        float o0 = fmaxf(0.0f, (v[j].x - m) * r * gv.x + bv.x);
        float o1 = fmaxf(0.0f, (v[j].y - m) * r * gv.y + bv.y);
        float o2 = fmaxf(0.0f, (v[j].z - m) * r * gv.z + bv.z);
        float o3 = fmaxf(0.0f, (v[j].w - m) * r * gv.w + bv.w);
        __half h0 = __float2half(o0), h1 = __float2half(o1);
        __half h2 = __float2half(o2), h3 = __float2half(o3);
        xh2[i4 * 2]     = __halves2half2(h0, h1);
        xh2[i4 * 2 + 1] = __halves2half2(h2, h3);
        xl2[i4 * 2]     = __halves2half2(__float2half(o0 - __half2float(h0)),
                                         __float2half(o1 - __half2float(h1)));
        xl2[i4 * 2 + 1] = __halves2half2(__float2half(o2 - __half2float(h2)),
                                         __float2half(o3 - __half2float(h3)));
    }
}

// ---------------- launcher ----------------
extern "C" void kernel_launch(void* const* d_in, const int* in_sizes, int n_in,
                              void* d_out, int out_size)
{
    const float* obs  = (const float*)d_in[0];
    const int*   am   = (const int*)  d_in[1];
    const float* gum  = (const float*)d_in[2];
    const float* W0   = (const float*)d_in[3];
    const float* b0   = (const float*)d_in[4];
    const float* g0   = (const float*)d_in[5];
    const float* be0  = (const float*)d_in[6];
    const float* W1   = (const float*)d_in[7];
    const float* b1   = (const float*)d_in[8];
    const float* g1   = (const float*)d_in[9];
    const float* be1  = (const float*)d_in[10];
    const float* W2   = (const float*)d_in[11];
    const float* b2   = (const float*)d_in[12];
    const float* g2   = (const float*)d_in[13];
    const float* be2  = (const float*)d_in[14];
    const float* Wp   = (const float*)d_in[15];
    const float* bp   = (const float*)d_in[16];
    const float* Wv   = (const float*)d_in[17];
    const float* bv   = (const float*)d_in[18];
    float* out = (float*)d_out;

    __half *A0h, *A0l, *B0h, *B0l, *B1h, *B1l, *B2h, *B2l, *Bhh, *Bhl, *Xh, *Xl;
    float *bh, *Y, *Ys;
    cudaGetSymbolAddress((void**)&A0h, g_A0h);
    cudaGetSymbolAddress((void**)&A0l, g_A0l);
    cudaGetSymbolAddress((void**)&B0h, g_B0h);
    cudaGetSymbolAddress((void**)&B0l, g_B0l);
    cudaGetSymbolAddress((void**)&B1h, g_B1h);
    cudaGetSymbolAddress((void**)&B1l, g_B1l);
    cudaGetSymbolAddress((void**)&B2h, g_B2h);
    cudaGetSymbolAddress((void**)&B2l, g_B2l);
    cudaGetSymbolAddress((void**)&Bhh, g_Bhh);
    cudaGetSymbolAddress((void**)&Bhl, g_Bhl);
    cudaGetSymbolAddress((void**)&bh,  g_bh);
    cudaGetSymbolAddress((void**)&Y,   g_Y);
    cudaGetSymbolAddress((void**)&Ys,  g_Ys);
    cudaGetSymbolAddress((void**)&Xh,  g_Xh);
    cudaGetSymbolAddress((void**)&Xl,  g_Xl);

    const int SMEM_BIG  = 3 * (128 * 128 + 16384) + 128;   // 96 KB + pad (IM=4)
    const int SMEM_HEAD = 3 * (32 * 128 + 16384) + 128;    // 60 KB + pad (head fused)
    cudaFuncSetAttribute(gemm_hmma<4>, cudaFuncAttributeMaxDynamicSharedMemorySize, SMEM_BIG);
    cudaFuncSetAttribute(head_sample_k, cudaFuncAttributeMaxDynamicSharedMemorySize, SMEM_HEAD);

    // --- side streams/events: created ONCE, reused every call (launched work
    //     per call is byte-identical; avoids per-call pool allocation that
    //     would outlive graph teardown) ---
    static cudaStream_t s2 = nullptr, s3 = nullptr;
    static cudaEvent_t evF = nullptr, evW0 = nullptr, evS3 = nullptr;
    if (s2 == nullptr) {
        cudaStreamCreateWithFlags(&s2, cudaStreamNonBlocking);
        cudaStreamCreateWithFlags(&s3, cudaStreamNonBlocking);
        cudaEventCreateWithFlags(&evF,  cudaEventDisableTiming);
        cudaEventCreateWithFlags(&evW0, cudaEventDisableTiming);
        cudaEventCreateWithFlags(&evS3, cudaEventDisableTiming);
    }

    cudaEventRecord(evF, 0);
    cudaStreamWaitEvent(s2, evF, 0);
    cudaStreamWaitEvent(s3, evF, 0);

    // main: obs split (gates L0 via stream order)
    split_obs_k<<<4096, 256>>>(obs);

    // s2: W0 transpose (gates L0)
    transpose_split_k<<<dim3(7168 / 32, 1024 / 32), dim3(32, 8), 0, s2>>>(W0, B0h, B0l, 7150, 7168, 1024);
    cudaEventRecord(evW0, s2);

    // s3: W1/W2/head prep — only needed before L1; overlaps L0 GEMM
    transpose_split_k<<<dim3(1024 / 32, 1024 / 32), dim3(32, 8), 0, s3>>>(W1, B1h, B1l, 1024, 1024, 1024);
    transpose_split_k<<<dim3(1024 / 32, 1024 / 32), dim3(32, 8), 0, s3>>>(W2, B2h, B2l, 1024, 1024, 1024);
    pack_head_k<<<(128 * 1024 + 255) / 256, 256, 0, s3>>>(Wp, bp, Wv, bv);
    cudaEventRecord(evS3, s3);

    cudaStreamWaitEvent(0, evW0, 0);

    // layer 0: split-K=4 (grid (8,32,4) = 1024 CTAs -> ~99% SM load balance)
    gemm_hmma<4><<<dim3(8, 32, 4), 256, SMEM_BIG>>>(A0h, A0l, B0h, B0l, b0, Ys, 1024, 7168, 56);
    ln4_relu_split_k<<<512, 256>>>(Ys, b0, g0, be0, Xh, Xl);

    cudaStreamWaitEvent(0, evS3, 0);      // W1/W2/head prep must be done by now

    dim3 grid1(1024 / 128, 4096 / 128);   // (8, 32)

    // layer 1
    gemm_hmma<4><<<grid1, 256, SMEM_BIG>>>(Xh, Xl, B1h, B1l, b1, Y, 1024, 1024, 32);
    ln_relu_split_k<<<512, 256>>>(Y, g1, be1, Xh, Xl);
    // layer 2
    gemm_hmma<4><<<grid1, 256, SMEM_BIG>>>(Xh, Xl, B2h, B2l, b2, Y, 1024, 1024, 32);
    ln_relu_split_k<<<512, 256>>>(Y, g2, be2, Xh, Xl);

    // fused head GEMM + sampling (BM=32 -> 128 CTAs)
    head_sample_k<<<dim3(1, 4096 / 32), 256, SMEM_HEAD>>>(Xh, Xl, Bhh, Bhl, bh, am, gum, out, 1024);
}

// round 15
// speedup vs baseline: 1.2492x; 1.0193x over previous
#include <cuda_runtime.h>
#include <cuda_fp16.h>
#include <cstdint>
#include <math.h>

#define NEGV (-1000000000.0f)
#define FLT_MAXV 3.402823466e38f

// ---------------- output layout ----------------
static const long OFF_LOGITS = 0;
static const long OFF_LP     = 385024;
static const long OFF_ACT    = 393216;
static const long OFF_VAL    = 401408;

#define SWZ128(x) ((x) ^ (((x) >> 3) & 0x70))

__device__ __forceinline__ uint32_t smem_to_u32(const void* p) {
    uint32_t a;
    asm("{ .reg .u64 t; cvta.to.shared.u64 t, %1; cvt.u32.u64 %0, t; }" : "=r"(a) : "l"(p));
    return a;
}
__device__ __forceinline__ void cp16(uint32_t sad, const void* gad) {
    asm volatile("cp.async.cg.shared.global [%0], [%1], 16;" :: "r"(sad), "l"(gad) : "memory");
}
__device__ __forceinline__ void ldm_x4(uint32_t* r, uint32_t addr) {
    asm volatile("ldmatrix.sync.aligned.m8n8.x4.shared.b16 {%0,%1,%2,%3}, [%4];"
                 : "=r"(r[0]), "=r"(r[1]), "=r"(r[2]), "=r"(r[3]) : "r"(addr));
}
__device__ __forceinline__ void mma16816(float* c, const uint32_t* a, const uint32_t* b) {
    asm volatile("mma.sync.aligned.m16n8k16.row.col.f32.f16.f16.f32 "
                 "{%0,%1,%2,%3}, {%4,%5,%6,%7}, {%8,%9}, {%0,%1,%2,%3};"
                 : "+f"(c[0]), "+f"(c[1]), "+f"(c[2]), "+f"(c[3])
                 : "r"(a[0]), "r"(a[1]), "r"(a[2]), "r"(a[3]), "r"(b[0]), "r"(b[1]));
}

// ---------------- scratch (device globals) ----------------
__device__ __half g_A0h[4096L * 7168];
__device__ __half g_A0l[4096L * 7168];
__device__ __half g_B0h[1024L * 7168];
__device__ __half g_B0l[1024L * 7168];
__device__ __half g_B1h[1024L * 1024];
__device__ __half g_B1l[1024L * 1024];
__device__ __half g_B2h[1024L * 1024];
__device__ __half g_B2l[1024L * 1024];
__device__ __half g_Bhh[128L * 1024];
__device__ __half g_Bhl[128L * 1024];
__device__ float  g_bh[128];
__device__ float  g_Ys[4L * 4096 * 1024];   // split-K partial sums
__device__ __half g_Xh[4096L * 1024];
__device__ __half g_Xl[4096L * 1024];

// ---------------- conversion kernels ----------------
// one block per row; float2 reads, half2 writes, no div/mod
__global__ void split_obs_k(const float* __restrict__ obs) {
    const int r   = blockIdx.x;
    const int tid = threadIdx.x;   // 256
    const float2* src = (const float2*)(obs + (size_t)r * 7150);   // 8B aligned
    __half2* dh = (__half2*)(g_A0h + (size_t)r * 7168);
    __half2* dl = (__half2*)(g_A0l + (size_t)r * 7168);
    #pragma unroll 4
    for (int i = tid; i < 3575; i += 256) {
        float2 v = src[i];
        __half hx = __float2half(v.x);
        __half hy = __float2half(v.y);
        dh[i] = __halves2half2(hx, hy);
        dl[i] = __halves2half2(__float2half(v.x - __half2float(hx)),
                               __float2half(v.y - __half2float(hy)));
    }
    if (tid < 9) {   // pad cols 7150..7167
        __half2 z = __float2half2_rn(0.0f);
        dh[3575 + tid] = z;
        dl[3575 + tid] = z;
    }
}

// W (K x N fp32) -> Bt hi/lo (N x Kpad fp16), transposed + split
__global__ void transpose_split_k(const float* __restrict__ W,
                                  __half* __restrict__ Bh,
                                  __half* __restrict__ Bl,
                                  int K, int Kpad, int N) {
    __shared__ float t[32][33];
    int k0 = blockIdx.x * 32, n0 = blockIdx.y * 32;
    int tx = threadIdx.x, ty = threadIdx.y;   // (32, 8)
    #pragma unroll
    for (int d = 0; d < 4; d++) {
        int k = k0 + ty + d * 8;
        t[ty + d * 8][tx] = (k < K) ? W[(size_t)k * N + n0 + tx] : 0.0f;
    }
    __syncthreads();
    #pragma unroll
    for (int d = 0; d < 4; d++) {
        int n = n0 + ty + d * 8;
        int k = k0 + tx;
        float x = t[tx][ty + d * 8];
        __half h = __float2half(x);
        Bh[(size_t)n * Kpad + k] = h;
        Bl[(size_t)n * Kpad + k] = __float2half(x - __half2float(h));
    }
}

__global__ void pack_head_k(const float* __restrict__ Wp, const float* __restrict__ bp,
                            const float* __restrict__ Wv, const float* __restrict__ bv) {
    int idx = blockIdx.x * blockDim.x + threadIdx.x;
    if (idx < 128 * 1024) {
        int n = idx / 1024;
        int k = idx % 1024;
        float x = 0.0f;
        if (n < 94)       x = Wp[(size_t)k * 94 + n];
        else if (n == 94) x = Wv[k];
        __half h = __float2half(x);
        g_Bhh[idx] = h;
        g_Bhl[idx] = __float2half(x - __half2float(h));
    }
    if (idx < 128) {
        float v = 0.0f;
        if (idx < 94)       v = bp[idx];
        else if (idx == 94) v = bv[0];
        g_bh[idx] = v;
    }
}

// ---------------- HMMA GEMM: C = A(MxK) @ Bt(NxK)^T ----------------
// 3-product fp16 split: Ahi@Bhi + Alo@Bhi + Ahi@Blo (all f32-acc; R6 optimum).
// CTA tile (IM*32) x 128, 8 warps; 3-stage cp.async, SW128, XOR-folded ldmatrix.
// Split-K: blockIdx.z processes nkcSplit k-chunks starting at z*nkcSplit and
// writes to partial buffer z (stride M*N). Bias is applied downstream (ln4/head).
template<int IM>
__global__ void __launch_bounds__(256, 2)
gemm_hmma(const __half* __restrict__ Ahi, const __half* __restrict__ Alo,
          const __half* __restrict__ Bhi, const __half* __restrict__ Blo,
          float* __restrict__ C, int N, int K, int nkcSplit)
{
    constexpr int BM = IM * 32;
    constexpr uint32_t A_BYTES = (uint32_t)BM * 128;
    constexpr uint32_t SSTRIDE = A_BYTES + 16384u;

    extern __shared__ char smem_raw[];
    const uint32_t sbase = (smem_to_u32(smem_raw) + 127u) & ~127u;   // 128B aligned
    const int tid  = threadIdx.x;
    const int wid  = tid >> 5;
    const int lane = tid & 31;
    const int bm   = blockIdx.y * BM;
    const int bn   = blockIdx.x * 128;
    const int wm   = (wid >> 2) * (IM * 16);
    const int wn   = (wid & 3) * 32;

    const int niter = nkcSplit;
    const int kc0   = blockIdx.z * nkcSplit;
    C += (size_t)blockIdx.z * (size_t)(gridDim.y * BM) * N;

    float acc[IM][4][4];
    #pragma unroll
    for (int im = 0; im < IM; im++)
        #pragma unroll
        for (int in = 0; in < 4; in++)
            #pragma unroll
            for (int j = 0; j < 4; j++) acc[im][in][j] = 0.0f;

    const int ldrow = tid >> 3;
    const int j7    = tid & 7;
    const int halfv = j7 >> 2;
    const int el16  = (j7 & 3) * 8;
    const uint32_t sAoff = SWZ128((uint32_t)(ldrow * 128 + j7 * 16));
    const uint32_t sBoff = A_BYTES + SWZ128((uint32_t)(ldrow * 128 + j7 * 16));
    const __half* Ag = (halfv ? Alo : Ahi) + (size_t)(bm + ldrow) * K + el16 + ((size_t)kc0 << 5);
    const __half* Bg = (halfv ? Blo : Bhi) + (size_t)(bn + ldrow) * K + el16 + ((size_t)kc0 << 5);
    const size_t gstepA = (size_t)32 * K;

    uint32_t so_ld = 0;
    auto load_stage = [&]() {
        #pragma unroll
        for (int j = 0; j < IM; j++)
            cp16(sbase + so_ld + sAoff + (uint32_t)j * 4096u, Ag + (size_t)j * gstepA);
        #pragma unroll
        for (int j = 0; j < 4; j++)
            cp16(sbase + so_ld + sBoff + (uint32_t)j * 4096u, Bg + (size_t)j * gstepA);
        Ag += 32; Bg += 32;
        so_ld += SSTRIDE;
        if (so_ld == 3 * SSTRIDE) so_ld = 0;
    };

    const int arow = wm + (lane & 15);
    const int asub = (lane >> 4) << 4;
    const int brow = wn + (lane & 7) + ((lane >> 4) << 3);
    const int bsub = ((lane >> 3) & 1) << 4;
    uint32_t offA[IM], offB[2];
    #pragma unroll
    for (int im = 0; im < IM; im++)
        offA[im] = SWZ128((uint32_t)(((arow + im * 16) << 7) + asub));
    #pragma unroll
    for (int ib = 0; ib < 2; ib++)
        offB[ib] = A_BYTES + SWZ128((uint32_t)(((brow + ib * 16) << 7) + bsub));

    load_stage();
    asm volatile("cp.async.commit_group;" ::: "memory");
    load_stage();
    asm volatile("cp.async.commit_group;" ::: "memory");

    uint32_t so_cm = 0;
    for (int t = 0; t < niter; t++) {
        asm volatile("cp.async.wait_group 1;" ::: "memory");
        __syncthreads();

        if (t + 2 < niter) load_stage();
        asm volatile("cp.async.commit_group;" ::: "memory");

        const uint32_t sa = sbase + so_cm;
        so_cm += SSTRIDE;
        if (so_cm == 3 * SSTRIDE) so_cm = 0;

        uint32_t aA[IM], aB[2];
        #pragma unroll
        for (int im = 0; im < IM; im++) aA[im] = sa + offA[im];
        #pragma unroll
        for (int ib = 0; ib < 2; ib++)  aB[ib] = sa + offB[ib];

        #pragma unroll
        for (int ks = 0; ks < 2; ks++) {
            const uint32_t kx = ks ? 32u : 0u;
            uint32_t bh[2][4], bl[2][4];
            #pragma unroll
            for (int ib = 0; ib < 2; ib++) {
                ldm_x4(bh[ib], aB[ib] ^ kx);
                ldm_x4(bl[ib], aB[ib] ^ (kx | 64u));
            }
            {
                uint32_t ah[IM][4];
                #pragma unroll
                for (int im = 0; im < IM; im++)
                    ldm_x4(ah[im], aA[im] ^ kx);
                #pragma unroll
                for (int im = 0; im < IM; im++)
                    #pragma unroll
                    for (int in = 0; in < 4; in++)
                        mma16816(acc[im][in], ah[im], &bh[in >> 1][(in & 1) * 2]);
                #pragma unroll
                for (int im = 0; im < IM; im++)
                    #pragma unroll
                    for (int in = 0; in < 4; in++)
                        mma16816(acc[im][in], ah[im], &bl[in >> 1][(in & 1) * 2]);
            }
            {
                uint32_t al[IM][4];
                #pragma unroll
                for (int im = 0; im < IM; im++)
                    ldm_x4(al[im], aA[im] ^ (kx | 64u));
                #pragma unroll
                for (int im = 0; im < IM; im++)
                    #pragma unroll
                    for (int in = 0; in < 4; in++)
                        mma16816(acc[im][in], al[im], &bh[in >> 1][(in & 1) * 2]);
            }
        }
    }

    // epilogue: direct stores (fragment-native layout)
    #pragma unroll
    for (int in = 0; in < 4; in++) {
        int col = bn + wn + in * 8 + ((lane & 3) << 1);
        #pragma unroll
        for (int im = 0; im < IM; im++) {
            int row = bm + wm + im * 16 + (lane >> 2);
            float2 v0 = { acc[im][in][0], acc[im][in][1] };
            float2 v1 = { acc[im][in][2], acc[im][in][3] };
            *(float2*)(C + (size_t)row * N + col)       = v0;
            *(float2*)(C + (size_t)(row + 8) * N + col) = v1;
        }
    }
}

// ---------------- FUSED head GEMM + sampling ----------------
// BM=32 rows per CTA, N=128 (cols 0..93 policy, 94 value), K=1024.
__global__ void __launch_bounds__(256, 2)
head_sample_k(const __half* __restrict__ Ahi, const __half* __restrict__ Alo,
              const __half* __restrict__ Bhi, const __half* __restrict__ Blo,
              const float* __restrict__ bias,
              const int* __restrict__ mask, const float* __restrict__ gum,
              float* __restrict__ out, int K)
{
    constexpr uint32_t A_BYTES = 32u * 128u;
    constexpr uint32_t SSTRIDE = A_BYTES + 16384u;

    extern __shared__ char smem_raw[];
    const uint32_t sbase = (smem_to_u32(smem_raw) + 127u) & ~127u;
    const int tid  = threadIdx.x;
    const int wid  = tid >> 5;
    const int lane = tid & 31;
    const int bm   = blockIdx.y * 32;
    const int wm   = (wid >> 2) * 16;
    const int wn   = (wid & 3) * 32;

    const int niter = K >> 5;

    float acc[4][4];
    #pragma unroll
    for (int in = 0; in < 4; in++)
        #pragma unroll
        for (int j = 0; j < 4; j++) acc[in][j] = 0.0f;

    const int ldrow = tid >> 3;
    const int j7    = tid & 7;
    const int halfv = j7 >> 2;
    const int el16  = (j7 & 3) * 8;
    const uint32_t sAoff = SWZ128((uint32_t)(ldrow * 128 + j7 * 16));
    const uint32_t sBoff = A_BYTES + SWZ128((uint32_t)(ldrow * 128 + j7 * 16));
    const __half* Ag = (halfv ? Alo : Ahi) + (size_t)(bm + ldrow) * K + el16;
    const __half* Bg = (halfv ? Blo : Bhi) + (size_t)ldrow * K + el16;
    const size_t gstepA = (size_t)32 * K;

    uint32_t so_ld = 0;
    auto load_stage = [&]() {
        cp16(sbase + so_ld + sAoff, Ag);
        #pragma unroll
        for (int j = 0; j < 4; j++)
            cp16(sbase + so_ld + sBoff + (uint32_t)j * 4096u, Bg + (size_t)j * gstepA);
        Ag += 32; Bg += 32;
        so_ld += SSTRIDE;
        if (so_ld == 3 * SSTRIDE) so_ld = 0;
    };

    const int arow = wm + (lane & 15);
    const int asub = (lane >> 4) << 4;
    const int brow = wn + (lane & 7) + ((lane >> 4) << 3);
    const int bsub = ((lane >> 3) & 1) << 4;
    const uint32_t offA0 = SWZ128((uint32_t)((arow << 7) + asub));
    uint32_t offB[2];
    #pragma unroll
    for (int ib = 0; ib < 2; ib++)
        offB[ib] = A_BYTES + SWZ128((uint32_t)(((brow + ib * 16) << 7) + bsub));

    load_stage();
    asm volatile("cp.async.commit_group;" ::: "memory");
    load_stage();
    asm volatile("cp.async.commit_group;" ::: "memory");

    uint32_t so_cm = 0;
    for (int t = 0; t < niter; t++) {
        asm volatile("cp.async.wait_group 1;" ::: "memory");
        __syncthreads();

        if (t + 2 < niter) load_stage();
        asm volatile("cp.async.commit_group;" ::: "memory");

        const uint32_t sa = sbase + so_cm;
        so_cm += SSTRIDE;
        if (so_cm == 3 * SSTRIDE) so_cm = 0;

        uint32_t aA0 = sa + offA0;
        uint32_t aB[2];
        #pragma unroll
        for (int ib = 0; ib < 2; ib++) aB[ib] = sa + offB[ib];

        #pragma unroll
        for (int ks = 0; ks < 2; ks++) {
            const uint32_t kx = ks ? 32u : 0u;
            uint32_t bh[2][4], bl[2][4];
            #pragma unroll
            for (int ib = 0; ib < 2; ib++) {
                ldm_x4(bh[ib], aB[ib] ^ kx);
                ldm_x4(bl[ib], aB[ib] ^ (kx | 64u));
            }
            {
                uint32_t ah[4];
                ldm_x4(ah, aA0 ^ kx);
                #pragma unroll
                for (int in = 0; in < 4; in++)
                    mma16816(acc[in], ah, &bh[in >> 1][(in & 1) * 2]);
                #pragma unroll
                for (int in = 0; in < 4; in++)
                    mma16816(acc[in], ah, &bl[in >> 1][(in & 1) * 2]);
            }
            {
                uint32_t al[4];
                ldm_x4(al, aA0 ^ (kx | 64u));
                #pragma unroll
                for (int in = 0; in < 4; in++)
                    mma16816(acc[in], al, &bh[in >> 1][(in & 1) * 2]);
            }
        }
    }

    // drain all pending cp.async before smem reuse
    asm volatile("cp.async.wait_group 0;" ::: "memory");
    __syncthreads();

    // stage results to smem: 32 rows x 128 cols, stride 132 floats
    float* scr = (float*)smem_raw;
    {
        int row = wm + (lane >> 2);
        #pragma unroll
        for (int in = 0; in < 4; in++) {
            int col = wn + in * 8 + ((lane & 3) << 1);
            float bx = bias[col], by = bias[col + 1];
            *(float2*)(scr + row * 132 + col)       = make_float2(acc[in][0] + bx, acc[in][1] + by);
            *(float2*)(scr + (row + 8) * 132 + col) = make_float2(acc[in][2] + bx, acc[in][3] + by);
        }
    }
    __syncthreads();

    // sampling: warp wid handles rows wid, wid+8, wid+16, wid+24
    #pragma unroll
    for (int rr = 0; rr < 4; rr++) {
        const int row = wid + rr * 8;
        const int b   = bm + row;
        const float* lr = scr + row * 132;

        for (int a = lane; a < 94; a += 32)
            out[OFF_LOGITS + (long)b * 94 + a] = lr[a];
        if (lane == 0)
            out[OFF_VAL + b] = lr[94];

        int a_prev = -1;
        #pragma unroll
        for (int j = 0; j < 2; j++) {
            int mk[2];
            #pragma unroll
            for (int t = 0; t < 2; t++) {
                int a = lane + 32 * t;
                int m = 0;
                if (a < 47) {
                    m = mask[(long)b * 94 + j * 47 + a];
                    if (j == 1) {
                        if (a_prev >= 1 && a_prev <= 6 && a == a_prev) m = 0;
                        if (a_prev > 26 && a_prev <= 46 && a >= 27)    m = 0;
                        if (a_prev == 0 && a == 0)                     m = 0;
                    }
                }
                mk[t] = m;
            }
            if (j == 1) {
                int ssum = mk[0] + mk[1];
                #pragma unroll
                for (int off = 16; off; off >>= 1)
                    ssum += __shfl_xor_sync(0xffffffffu, ssum, off);
                if (ssum == 0 && a_prev == 0 && lane == 0) mk[0] = 1;
            }

            float lv[2], key[2];
            #pragma unroll
            for (int t = 0; t < 2; t++) {
                int a = lane + 32 * t;
                if (a < 47) {
                    float lg = lr[j * 47 + a];
                    lv[t]  = mk[t] ? lg : NEGV;
                    key[t] = lv[t] + gum[(long)b * 94 + j * 47 + a];
                } else {
                    lv[t]  = -FLT_MAXV;
                    key[t] = -FLT_MAXV;
                }
            }

            float bk = key[0]; int bi = lane;
            if (key[1] > bk) { bk = key[1]; bi = lane + 32; }
            #pragma unroll
            for (int off = 16; off; off >>= 1) {
                float ok = __shfl_xor_sync(0xffffffffu, bk, off);
                int   oi = __shfl_xor_sync(0xffffffffu, bi, off);
                if (ok > bk || (ok == bk && oi < bi)) { bk = ok; bi = oi; }
            }

            float mx = fmaxf(lv[0], lv[1]);
            #pragma unroll
            for (int off = 16; off; off >>= 1)
                mx = fmaxf(mx, __shfl_xor_sync(0xffffffffu, mx, off));
            float es = 0.0f;
            if (lane      < 47) es += expf(lv[0] - mx);
            if (lane + 32 < 47) es += expf(lv[1] - mx);
            #pragma unroll
            for (int off = 16; off; off >>= 1)
                es += __shfl_xor_sync(0xffffffffu, es, off);

            float lsel = __shfl_sync(0xffffffffu, lv[bi >= 32 ? 1 : 0], bi & 31);
            float logp = lsel - mx - logf(es);

            if (lane == 0) {
                out[OFF_LP  + (long)b * 2 + j] = logp;
                out[OFF_ACT + (long)b * 2 + j] = (float)bi;
            }
            a_prev = bi;
        }
    }
}

// ---------------- LN: sum 4 split-K partials + bias, ReLU, fp16 split ----------
__global__ void __launch_bounds__(256)
ln4_relu_split_k(const float* __restrict__ Ys, const float* __restrict__ bias,
                 const float* __restrict__ g, const float* __restrict__ be,
                 __half* __restrict__ Xh, __half* __restrict__ Xl)
{
    const int wid  = threadIdx.x >> 5;
    const int lane = threadIdx.x & 31;
    const int row  = blockIdx.x * 8 + wid;
    const size_t PART = 4096L * 1024;

    const float4* r0 = (const float4*)(Ys + (size_t)row * 1024);
    const float4* r1 = (const float4*)(Ys + PART     + (size_t)row * 1024);
    const float4* r2 = (const float4*)(Ys + PART * 2 + (size_t)row * 1024);
    const float4* r3 = (const float4*)(Ys + PART * 3 + (size_t)row * 1024);

    float4 v[8];
    float s = 0.0f, q = 0.0f;
    #pragma unroll
    for (int j = 0; j < 8; j++) {
        const int i4 = lane + j * 32;
        float4 a = __ldcs(r0 + i4), b = __ldcs(r1 + i4);
        float4 c = __ldcs(r2 + i4), d = __ldcs(r3 + i4);
        float4 bs = ((const float4*)bias)[i4];
        v[j].x = a.x + b.x + c.x + d.x + bs.x;
        v[j].y = a.y + b.y + c.y + d.y + bs.y;
        v[j].z = a.z + b.z + c.z + d.z + bs.z;
        v[j].w = a.w + b.w + c.w + d.w + bs.w;
        s += v[j].x + v[j].y + v[j].z + v[j].w;
        q += v[j].x * v[j].x + v[j].y * v[j].y + v[j].z * v[j].z + v[j].w * v[j].w;
    }
    #pragma unroll
    for (int o = 16; o; o >>= 1) {
        s += __shfl_xor_sync(0xffffffffu, s, o);
        q += __shfl_xor_sync(0xffffffffu, q, o);
    }
    const float m = s * (1.0f / 1024.0f);
    const float r = rsqrtf(q * (1.0f / 1024.0f) - m * m + 1e-5f);

    __half2* xh2 = (__half2*)(Xh + (size_t)row * 1024);
    __half2* xl2 = (__half2*)(Xl + (size_t)row * 1024);
    #pragma unroll
    for (int j = 0; j < 8; j++) {
        const int i4 = lane + j * 32;
        float4 gv = ((const float4*)g)[i4];
        float4 bv = ((const float4*)be)[i4];
        float o0 = fmaxf(0.0f, (v[j].x - m) * r * gv.x + bv.x);
        float o1 = fmaxf(0.0f, (v[j].y - m) * r * gv.y + bv.y);
        float o2 = fmaxf(0.0f, (v[j].z - m) * r * gv.z + bv.z);
        float o3 = fmaxf(0.0f, (v[j].w - m) * r * gv.w + bv.w);
        __half h0 = __float2half(o0), h1 = __float2half(o1);
        __half h2 = __float2half(o2), h3 = __float2half(o3);
        xh2[i4 * 2]     = __halves2half2(h0, h1);
        xh2[i4 * 2 + 1] = __halves2half2(h2, h3);
        xl2[i4 * 2]     = __halves2half2(__float2half(o0 - __half2float(h0)),
                                         __float2half(o1 - __half2float(h1)));
        xl2[i4 * 2 + 1] = __halves2half2(__float2half(o2 - __half2float(h2)),
                                         __float2half(o3 - __half2float(h3)));
    }
}

// ---------------- launcher ----------------
extern "C" void kernel_launch(void* const* d_in, const int* in_sizes, int n_in,
                              void* d_out, int out_size)
{
    const float* obs  = (const float*)d_in[0];
    const int*   am   = (const int*)  d_in[1];
    const float* gum  = (const float*)d_in[2];
    const float* W0   = (const float*)d_in[3];
    const float* b0   = (const float*)d_in[4];
    const float* g0   = (const float*)d_in[5];
    const float* be0  = (const float*)d_in[6];
    const float* W1   = (const float*)d_in[7];
    const float* b1   = (const float*)d_in[8];
    const float* g1   = (const float*)d_in[9];
    const float* be1  = (const float*)d_in[10];
    const float* W2   = (const float*)d_in[11];
    const float* b2   = (const float*)d_in[12];
    const float* g2   = (const float*)d_in[13];
    const float* be2  = (const float*)d_in[14];
    const float* Wp   = (const float*)d_in[15];
    const float* bp   = (const float*)d_in[16];
    const float* Wv   = (const float*)d_in[17];
    const float* bv   = (const float*)d_in[18];
    float* out = (float*)d_out;

    __half *A0h, *A0l, *B0h, *B0l, *B1h, *B1l, *B2h, *B2l, *Bhh, *Bhl, *Xh, *Xl;
    float *bh, *Ys;
    cudaGetSymbolAddress((void**)&A0h, g_A0h);
    cudaGetSymbolAddress((void**)&A0l, g_A0l);
    cudaGetSymbolAddress((void**)&B0h, g_B0h);
    cudaGetSymbolAddress((void**)&B0l, g_B0l);
    cudaGetSymbolAddress((void**)&B1h, g_B1h);
    cudaGetSymbolAddress((void**)&B1l, g_B1l);
    cudaGetSymbolAddress((void**)&B2h, g_B2h);
    cudaGetSymbolAddress((void**)&B2l, g_B2l);
    cudaGetSymbolAddress((void**)&Bhh, g_Bhh);
    cudaGetSymbolAddress((void**)&Bhl, g_Bhl);
    cudaGetSymbolAddress((void**)&bh,  g_bh);
    cudaGetSymbolAddress((void**)&Ys,  g_Ys);
    cudaGetSymbolAddress((void**)&Xh,  g_Xh);
    cudaGetSymbolAddress((void**)&Xl,  g_Xl);

    const int SMEM_BIG  = 3 * (128 * 128 + 16384) + 128;   // 96 KB + pad (IM=4)
    const int SMEM_HEAD = 3 * (32 * 128 + 16384) + 128;    // 60 KB + pad (head fused)
    cudaFuncSetAttribute(gemm_hmma<4>, cudaFuncAttributeMaxDynamicSharedMemorySize, SMEM_BIG);
    cudaFuncSetAttribute(head_sample_k, cudaFuncAttributeMaxDynamicSharedMemorySize, SMEM_HEAD);

    // --- side streams/events: created ONCE, reused every call (launched work
    //     per call is byte-identical; avoids per-call pool allocation that
    //     would outlive graph teardown) ---
    static cudaStream_t s2 = nullptr, s3 = nullptr;
    static cudaEvent_t evF = nullptr, evW0 = nullptr, evS3 = nullptr;
    if (s2 == nullptr) {
        cudaStreamCreateWithFlags(&s2, cudaStreamNonBlocking);
        cudaStreamCreateWithFlags(&s3, cudaStreamNonBlocking);
        cudaEventCreateWithFlags(&evF,  cudaEventDisableTiming);
        cudaEventCreateWithFlags(&evW0, cudaEventDisableTiming);
        cudaEventCreateWithFlags(&evS3, cudaEventDisableTiming);
    }

    cudaEventRecord(evF, 0);
    cudaStreamWaitEvent(s2, evF, 0);
    cudaStreamWaitEvent(s3, evF, 0);

    // main: obs split (gates L0 via stream order)
    split_obs_k<<<4096, 256>>>(obs);

    // s2: W0 transpose (gates L0)
    transpose_split_k<<<dim3(7168 / 32, 1024 / 32), dim3(32, 8), 0, s2>>>(W0, B0h, B0l, 7150, 7168, 1024);
    cudaEventRecord(evW0, s2);

    // s3: W1/W2/head prep — only needed before L1; overlaps L0 GEMM
    transpose_split_k<<<dim3(1024 / 32, 1024 / 32), dim3(32, 8), 0, s3>>>(W1, B1h, B1l, 1024, 1024, 1024);
    transpose_split_k<<<dim3(1024 / 32, 1024 / 32), dim3(32, 8), 0, s3>>>(W2, B2h, B2l, 1024, 1024, 1024);
    pack_head_k<<<(128 * 1024 + 255) / 256, 256, 0, s3>>>(Wp, bp, Wv, bv);
    cudaEventRecord(evS3, s3);

    cudaStreamWaitEvent(0, evW0, 0);

    // layer 0: split-K=4 (1024 CTAs -> ~99% SM load balance)
    gemm_hmma<4><<<dim3(8, 32, 4), 256, SMEM_BIG>>>(A0h, A0l, B0h, B0l, Ys, 1024, 7168, 56);
    ln4_relu_split_k<<<512, 256>>>(Ys, b0, g0, be0, Xh, Xl);

    cudaStreamWaitEvent(0, evS3, 0);      // W1/W2/head prep must be done by now

    // layer 1: split-K=4 (partials stay L2-resident; operands are small)
    gemm_hmma<4><<<dim3(8, 32, 4), 256, SMEM_BIG>>>(Xh, Xl, B1h, B1l, Ys, 1024, 1024, 8);
    ln4_relu_split_k<<<512, 256>>>(Ys, b1, g1, be1, Xh, Xl);
    // layer 2: split-K=4
    gemm_hmma<4><<<dim3(8, 32, 4), 256, SMEM_BIG>>>(Xh, Xl, B2h, B2l, Ys, 1024, 1024, 8);
    ln4_relu_split_k<<<512, 256>>>(Ys, b2, g2, be2, Xh, Xl);

    // fused head GEMM + sampling (BM=32 -> 128 CTAs)
    head_sample_k<<<dim3(1, 4096 / 32), 256, SMEM_HEAD>>>(Xh, Xl, Bhh, Bhl, bh, am, gum, out, 1024);
}

// round 16
// speedup vs baseline: 1.2532x; 1.0032x over previous
#include <cuda_runtime.h>
#include <cuda_fp16.h>
#include <cstdint>
#include <math.h>

#define NEGV (-1000000000.0f)
#define FLT_MAXV 3.402823466e38f

// ---------------- output layout ----------------
static const long OFF_LOGITS = 0;
static const long OFF_LP     = 385024;
static const long OFF_ACT    = 393216;
static const long OFF_VAL    = 401408;

#define SWZ128(x) ((x) ^ (((x) >> 3) & 0x70))

__device__ __forceinline__ uint32_t smem_to_u32(const void* p) {
    uint32_t a;
    asm("{ .reg .u64 t; cvta.to.shared.u64 t, %1; cvt.u32.u64 %0, t; }" : "=r"(a) : "l"(p));
    return a;
}
__device__ __forceinline__ void cp16(uint32_t sad, const void* gad) {
    asm volatile("cp.async.cg.shared.global [%0], [%1], 16;" :: "r"(sad), "l"(gad) : "memory");
}
__device__ __forceinline__ void ldm_x4(uint32_t* r, uint32_t addr) {
    asm volatile("ldmatrix.sync.aligned.m8n8.x4.shared.b16 {%0,%1,%2,%3}, [%4];"
                 : "=r"(r[0]), "=r"(r[1]), "=r"(r[2]), "=r"(r[3]) : "r"(addr));
}
__device__ __forceinline__ void mma16816(float* c, const uint32_t* a, const uint32_t* b) {
    asm volatile("mma.sync.aligned.m16n8k16.row.col.f32.f16.f16.f32 "
                 "{%0,%1,%2,%3}, {%4,%5,%6,%7}, {%8,%9}, {%0,%1,%2,%3};"
                 : "+f"(c[0]), "+f"(c[1]), "+f"(c[2]), "+f"(c[3])
                 : "r"(a[0]), "r"(a[1]), "r"(a[2]), "r"(a[3]), "r"(b[0]), "r"(b[1]));
}

// ---------------- scratch (device globals) ----------------
__device__ __half g_A0h[4096L * 7168];
__device__ __half g_A0l[4096L * 7168];
__device__ __half g_B0h[1024L * 7168];
__device__ __half g_B0l[1024L * 7168];
__device__ __half g_B1h[1024L * 1024];
__device__ __half g_B1l[1024L * 1024];
__device__ __half g_B2h[1024L * 1024];
__device__ __half g_B2l[1024L * 1024];
__device__ __half g_Bhh[128L * 1024];
__device__ __half g_Bhl[128L * 1024];
__device__ float  g_bh[128];
__device__ float  g_Ys[4L * 4096 * 1024];   // split-K partial sums
__device__ __half g_Xh[4096L * 1024];
__device__ __half g_Xl[4096L * 1024];

// ---------------- conversion kernels ----------------
// one block per row; float2 reads, half2 writes, no div/mod
__global__ void split_obs_k(const float* __restrict__ obs) {
    const int r   = blockIdx.x;
    const int tid = threadIdx.x;   // 256
    const float2* src = (const float2*)(obs + (size_t)r * 7150);   // 8B aligned
    __half2* dh = (__half2*)(g_A0h + (size_t)r * 7168);
    __half2* dl = (__half2*)(g_A0l + (size_t)r * 7168);
    #pragma unroll 4
    for (int i = tid; i < 3575; i += 256) {
        float2 v = src[i];
        __half hx = __float2half(v.x);
        __half hy = __float2half(v.y);
        dh[i] = __halves2half2(hx, hy);
        dl[i] = __halves2half2(__float2half(v.x - __half2float(hx)),
                               __float2half(v.y - __half2float(hy)));
    }
    if (tid < 9) {   // pad cols 7150..7167
        __half2 z = __float2half2_rn(0.0f);
        dh[3575 + tid] = z;
        dl[3575 + tid] = z;
    }
}

// W (K x N fp32) -> Bt hi/lo (N x Kpad fp16), transposed + split.
// 64(k) x 32(n) tile; smem n-major (conflict-free fills); half2 stores along k
// -> 128B-coalesced warp stores for both Bh and Bl.
__global__ void transpose_split_k(const float* __restrict__ W,
                                  __half* __restrict__ Bh,
                                  __half* __restrict__ Bl,
                                  int K, int Kpad, int N) {
    __shared__ float t[32][65];          // [n_local][k_local]
    const int k0 = blockIdx.x * 64, n0 = blockIdx.y * 32;
    const int tx = threadIdx.x, ty = threadIdx.y;   // (32, 8)
    #pragma unroll
    for (int d = 0; d < 8; d++) {
        int ky = ty + d * 8;             // 0..63
        int k  = k0 + ky;
        t[tx][ky] = (k < K) ? W[(size_t)k * N + n0 + tx] : 0.0f;
    }
    __syncthreads();
    #pragma unroll
    for (int d = 0; d < 4; d++) {
        int nl = ty + d * 8;
        int n  = n0 + nl;
        float x0 = t[nl][2 * tx];
        float x1 = t[nl][2 * tx + 1];
        __half h0 = __float2half(x0), h1 = __float2half(x1);
        __half l0 = __float2half(x0 - __half2float(h0));
        __half l1 = __float2half(x1 - __half2float(h1));
        *(__half2*)(Bh + (size_t)n * Kpad + k0 + 2 * tx) = __halves2half2(h0, h1);
        *(__half2*)(Bl + (size_t)n * Kpad + k0 + 2 * tx) = __halves2half2(l0, l1);
    }
}

__global__ void pack_head_k(const float* __restrict__ Wp, const float* __restrict__ bp,
                            const float* __restrict__ Wv, const float* __restrict__ bv) {
    int idx = blockIdx.x * blockDim.x + threadIdx.x;
    if (idx < 128 * 1024) {
        int n = idx / 1024;
        int k = idx % 1024;
        float x = 0.0f;
        if (n < 94)       x = Wp[(size_t)k * 94 + n];
        else if (n == 94) x = Wv[k];
        __half h = __float2half(x);
        g_Bhh[idx] = h;
        g_Bhl[idx] = __float2half(x - __half2float(h));
    }
    if (idx < 128) {
        float v = 0.0f;
        if (idx < 94)       v = bp[idx];
        else if (idx == 94) v = bv[0];
        g_bh[idx] = v;
    }
}

// ---------------- HMMA GEMM: C = A(MxK) @ Bt(NxK)^T ----------------
// 3-product fp16 split: Ahi@Bhi + Alo@Bhi + Ahi@Blo (all f32-acc; R6 optimum).
// CTA tile (IM*32) x 128, 8 warps; 3-stage cp.async, SW128, XOR-folded ldmatrix.
// Split-K: blockIdx.z processes nkcSplit k-chunks starting at z*nkcSplit and
// writes to partial buffer z (stride M*N). Bias is applied downstream (ln4/head).
template<int IM>
__global__ void __launch_bounds__(256, 2)
gemm_hmma(const __half* __restrict__ Ahi, const __half* __restrict__ Alo,
          const __half* __restrict__ Bhi, const __half* __restrict__ Blo,
          float* __restrict__ C, int N, int K, int nkcSplit)
{
    constexpr int BM = IM * 32;
    constexpr uint32_t A_BYTES = (uint32_t)BM * 128;
    constexpr uint32_t SSTRIDE = A_BYTES + 16384u;

    extern __shared__ char smem_raw[];
    const uint32_t sbase = (smem_to_u32(smem_raw) + 127u) & ~127u;   // 128B aligned
    const int tid  = threadIdx.x;
    const int wid  = tid >> 5;
    const int lane = tid & 31;
    const int bm   = blockIdx.y * BM;
    const int bn   = blockIdx.x * 128;
    const int wm   = (wid >> 2) * (IM * 16);
    const int wn   = (wid & 3) * 32;

    const int niter = nkcSplit;
    const int kc0   = blockIdx.z * nkcSplit;
    C += (size_t)blockIdx.z * (size_t)(gridDim.y * BM) * N;

    float acc[IM][4][4];
    #pragma unroll
    for (int im = 0; im < IM; im++)
        #pragma unroll
        for (int in = 0; in < 4; in++)
            #pragma unroll
            for (int j = 0; j < 4; j++) acc[im][in][j] = 0.0f;

    const int ldrow = tid >> 3;
    const int j7    = tid & 7;
    const int halfv = j7 >> 2;
    const int el16  = (j7 & 3) * 8;
    const uint32_t sAoff = SWZ128((uint32_t)(ldrow * 128 + j7 * 16));
    const uint32_t sBoff = A_BYTES + SWZ128((uint32_t)(ldrow * 128 + j7 * 16));
    const __half* Ag = (halfv ? Alo : Ahi) + (size_t)(bm + ldrow) * K + el16 + ((size_t)kc0 << 5);
    const __half* Bg = (halfv ? Blo : Bhi) + (size_t)(bn + ldrow) * K + el16 + ((size_t)kc0 << 5);
    const size_t gstepA = (size_t)32 * K;

    uint32_t so_ld = 0;
    auto load_stage = [&]() {
        #pragma unroll
        for (int j = 0; j < IM; j++)
            cp16(sbase + so_ld + sAoff + (uint32_t)j * 4096u, Ag + (size_t)j * gstepA);
        #pragma unroll
        for (int j = 0; j < 4; j++)
            cp16(sbase + so_ld + sBoff + (uint32_t)j * 4096u, Bg + (size_t)j * gstepA);
        Ag += 32; Bg += 32;
        so_ld += SSTRIDE;
        if (so_ld == 3 * SSTRIDE) so_ld = 0;
    };

    const int arow = wm + (lane & 15);
    const int asub = (lane >> 4) << 4;
    const int brow = wn + (lane & 7) + ((lane >> 4) << 3);
    const int bsub = ((lane >> 3) & 1) << 4;
    uint32_t offA[IM], offB[2];
    #pragma unroll
    for (int im = 0; im < IM; im++)
        offA[im] = SWZ128((uint32_t)(((arow + im * 16) << 7) + asub));
    #pragma unroll
    for (int ib = 0; ib < 2; ib++)
        offB[ib] = A_BYTES + SWZ128((uint32_t)(((brow + ib * 16) << 7) + bsub));

    load_stage();
    asm volatile("cp.async.commit_group;" ::: "memory");
    load_stage();
    asm volatile("cp.async.commit_group;" ::: "memory");

    uint32_t so_cm = 0;
    for (int t = 0; t < niter; t++) {
        asm volatile("cp.async.wait_group 1;" ::: "memory");
        __syncthreads();

        if (t + 2 < niter) load_stage();
        asm volatile("cp.async.commit_group;" ::: "memory");

        const uint32_t sa = sbase + so_cm;
        so_cm += SSTRIDE;
        if (so_cm == 3 * SSTRIDE) so_cm = 0;

        uint32_t aA[IM], aB[2];
        #pragma unroll
        for (int im = 0; im < IM; im++) aA[im] = sa + offA[im];
        #pragma unroll
        for (int ib = 0; ib < 2; ib++)  aB[ib] = sa + offB[ib];

        #pragma unroll
        for (int ks = 0; ks < 2; ks++) {
            const uint32_t kx = ks ? 32u : 0u;
            uint32_t bh[2][4], bl[2][4];
            #pragma unroll
            for (int ib = 0; ib < 2; ib++) {
                ldm_x4(bh[ib], aB[ib] ^ kx);
                ldm_x4(bl[ib], aB[ib] ^ (kx | 64u));
            }
            {
                uint32_t ah[IM][4];
                #pragma unroll
                for (int im = 0; im < IM; im++)
                    ldm_x4(ah[im], aA[im] ^ kx);
                #pragma unroll
                for (int im = 0; im < IM; im++)
                    #pragma unroll
                    for (int in = 0; in < 4; in++)
                        mma16816(acc[im][in], ah[im], &bh[in >> 1][(in & 1) * 2]);
                #pragma unroll
                for (int im = 0; im < IM; im++)
                    #pragma unroll
                    for (int in = 0; in < 4; in++)
                        mma16816(acc[im][in], ah[im], &bl[in >> 1][(in & 1) * 2]);
            }
            {
                uint32_t al[IM][4];
                #pragma unroll
                for (int im = 0; im < IM; im++)
                    ldm_x4(al[im], aA[im] ^ (kx | 64u));
                #pragma unroll
                for (int im = 0; im < IM; im++)
                    #pragma unroll
                    for (int in = 0; in < 4; in++)
                        mma16816(acc[im][in], al[im], &bh[in >> 1][(in & 1) * 2]);
            }
        }
    }

    // epilogue: direct stores (fragment-native layout)
    #pragma unroll
    for (int in = 0; in < 4; in++) {
        int col = bn + wn + in * 8 + ((lane & 3) << 1);
        #pragma unroll
        for (int im = 0; im < IM; im++) {
            int row = bm + wm + im * 16 + (lane >> 2);
            float2 v0 = { acc[im][in][0], acc[im][in][1] };
            float2 v1 = { acc[im][in][2], acc[im][in][3] };
            *(float2*)(C + (size_t)row * N + col)       = v0;
            *(float2*)(C + (size_t)(row + 8) * N + col) = v1;
        }
    }
}

// ---------------- FUSED head GEMM + sampling ----------------
// BM=32 rows per CTA, N=128 (cols 0..93 policy, 94 value), K=1024.
__global__ void __launch_bounds__(256, 2)
head_sample_k(const __half* __restrict__ Ahi, const __half* __restrict__ Alo,
              const __half* __restrict__ Bhi, const __half* __restrict__ Blo,
              const float* __restrict__ bias,
              const int* __restrict__ mask, const float* __restrict__ gum,
              float* __restrict__ out, int K)
{
    constexpr uint32_t A_BYTES = 32u * 128u;
    constexpr uint32_t SSTRIDE = A_BYTES + 16384u;

    extern __shared__ char smem_raw[];
    const uint32_t sbase = (smem_to_u32(smem_raw) + 127u) & ~127u;
    const int tid  = threadIdx.x;
    const int wid  = tid >> 5;
    const int lane = tid & 31;
    const int bm   = blockIdx.y * 32;
    const int wm   = (wid >> 2) * 16;
    const int wn   = (wid & 3) * 32;

    const int niter = K >> 5;

    float acc[4][4];
    #pragma unroll
    for (int in = 0; in < 4; in++)
        #pragma unroll
        for (int j = 0; j < 4; j++) acc[in][j] = 0.0f;

    const int ldrow = tid >> 3;
    const int j7    = tid & 7;
    const int halfv = j7 >> 2;
    const int el16  = (j7 & 3) * 8;
    const uint32_t sAoff = SWZ128((uint32_t)(ldrow * 128 + j7 * 16));
    const uint32_t sBoff = A_BYTES + SWZ128((uint32_t)(ldrow * 128 + j7 * 16));
    const __half* Ag = (halfv ? Alo : Ahi) + (size_t)(bm + ldrow) * K + el16;
    const __half* Bg = (halfv ? Blo : Bhi) + (size_t)ldrow * K + el16;
    const size_t gstepA = (size_t)32 * K;

    uint32_t so_ld = 0;
    auto load_stage = [&]() {
        cp16(sbase + so_ld + sAoff, Ag);
        #pragma unroll
        for (int j = 0; j < 4; j++)
            cp16(sbase + so_ld + sBoff + (uint32_t)j * 4096u, Bg + (size_t)j * gstepA);
        Ag += 32; Bg += 32;
        so_ld += SSTRIDE;
        if (so_ld == 3 * SSTRIDE) so_ld = 0;
    };

    const int arow = wm + (lane & 15);
    const int asub = (lane >> 4) << 4;
    const int brow = wn + (lane & 7) + ((lane >> 4) << 3);
    const int bsub = ((lane >> 3) & 1) << 4;
    const uint32_t offA0 = SWZ128((uint32_t)((arow << 7) + asub));
    uint32_t offB[2];
    #pragma unroll
    for (int ib = 0; ib < 2; ib++)
        offB[ib] = A_BYTES + SWZ128((uint32_t)(((brow + ib * 16) << 7) + bsub));

    load_stage();
    asm volatile("cp.async.commit_group;" ::: "memory");
    load_stage();
    asm volatile("cp.async.commit_group;" ::: "memory");

    uint32_t so_cm = 0;
    for (int t = 0; t < niter; t++) {
        asm volatile("cp.async.wait_group 1;" ::: "memory");
        __syncthreads();

        if (t + 2 < niter) load_stage();
        asm volatile("cp.async.commit_group;" ::: "memory");

        const uint32_t sa = sbase + so_cm;
        so_cm += SSTRIDE;
        if (so_cm == 3 * SSTRIDE) so_cm = 0;

        uint32_t aA0 = sa + offA0;
        uint32_t aB[2];
        #pragma unroll
        for (int ib = 0; ib < 2; ib++) aB[ib] = sa + offB[ib];

        #pragma unroll
        for (int ks = 0; ks < 2; ks++) {
            const uint32_t kx = ks ? 32u : 0u;
            uint32_t bh[2][4], bl[2][4];
            #pragma unroll
            for (int ib = 0; ib < 2; ib++) {
                ldm_x4(bh[ib], aB[ib] ^ kx);
                ldm_x4(bl[ib], aB[ib] ^ (kx | 64u));
            }
            {
                uint32_t ah[4];
                ldm_x4(ah, aA0 ^ kx);
                #pragma unroll
                for (int in = 0; in < 4; in++)
                    mma16816(acc[in], ah, &bh[in >> 1][(in & 1) * 2]);
                #pragma unroll
                for (int in = 0; in < 4; in++)
                    mma16816(acc[in], ah, &bl[in >> 1][(in & 1) * 2]);
            }
            {
                uint32_t al[4];
                ldm_x4(al, aA0 ^ (kx | 64u));
                #pragma unroll
                for (int in = 0; in < 4; in++)
                    mma16816(acc[in], al, &bh[in >> 1][(in & 1) * 2]);
            }
        }
    }

    // drain all pending cp.async before smem reuse
    asm volatile("cp.async.wait_group 0;" ::: "memory");
    __syncthreads();

    // stage results to smem: 32 rows x 128 cols, stride 132 floats
    float* scr = (float*)smem_raw;
    {
        int row = wm + (lane >> 2);
        #pragma unroll
        for (int in = 0; in < 4; in++) {
            int col = wn + in * 8 + ((lane & 3) << 1);
            float bx = bias[col], by = bias[col + 1];
            *(float2*)(scr + row * 132 + col)       = make_float2(acc[in][0] + bx, acc[in][1] + by);
            *(float2*)(scr + (row + 8) * 132 + col) = make_float2(acc[in][2] + bx, acc[in][3] + by);
        }
    }
    __syncthreads();

    // sampling: warp wid handles rows wid, wid+8, wid+16, wid+24
    #pragma unroll
    for (int rr = 0; rr < 4; rr++) {
        const int row = wid + rr * 8;
        const int b   = bm + row;
        const float* lr = scr + row * 132;

        for (int a = lane; a < 94; a += 32)
            out[OFF_LOGITS + (long)b * 94 + a] = lr[a];
        if (lane == 0)
            out[OFF_VAL + b] = lr[94];

        int a_prev = -1;
        #pragma unroll
        for (int j = 0; j < 2; j++) {
            int mk[2];
            #pragma unroll
            for (int t = 0; t < 2; t++) {
                int a = lane + 32 * t;
                int m = 0;
                if (a < 47) {
                    m = mask[(long)b * 94 + j * 47 + a];
                    if (j == 1) {
                        if (a_prev >= 1 && a_prev <= 6 && a == a_prev) m = 0;
                        if (a_prev > 26 && a_prev <= 46 && a >= 27)    m = 0;
                        if (a_prev == 0 && a == 0)                     m = 0;
                    }
                }
                mk[t] = m;
            }
            if (j == 1) {
                int ssum = mk[0] + mk[1];
                #pragma unroll
                for (int off = 16; off; off >>= 1)
                    ssum += __shfl_xor_sync(0xffffffffu, ssum, off);
                if (ssum == 0 && a_prev == 0 && lane == 0) mk[0] = 1;
            }

            float lv[2], key[2];
            #pragma unroll
            for (int t = 0; t < 2; t++) {
                int a = lane + 32 * t;
                if (a < 47) {
                    float lg = lr[j * 47 + a];
                    lv[t]  = mk[t] ? lg : NEGV;
                    key[t] = lv[t] + gum[(long)b * 94 + j * 47 + a];
                } else {
                    lv[t]  = -FLT_MAXV;
                    key[t] = -FLT_MAXV;
                }
            }

            float bk = key[0]; int bi = lane;
            if (key[1] > bk) { bk = key[1]; bi = lane + 32; }
            #pragma unroll
            for (int off = 16; off; off >>= 1) {
                float ok = __shfl_xor_sync(0xffffffffu, bk, off);
                int   oi = __shfl_xor_sync(0xffffffffu, bi, off);
                if (ok > bk || (ok == bk && oi < bi)) { bk = ok; bi = oi; }
            }

            float mx = fmaxf(lv[0], lv[1]);
            #pragma unroll
            for (int off = 16; off; off >>= 1)
                mx = fmaxf(mx, __shfl_xor_sync(0xffffffffu, mx, off));
            float es = 0.0f;
            if (lane      < 47) es += expf(lv[0] - mx);
            if (lane + 32 < 47) es += expf(lv[1] - mx);
            #pragma unroll
            for (int off = 16; off; off >>= 1)
                es += __shfl_xor_sync(0xffffffffu, es, off);

            float lsel = __shfl_sync(0xffffffffu, lv[bi >= 32 ? 1 : 0], bi & 31);
            float logp = lsel - mx - logf(es);

            if (lane == 0) {
                out[OFF_LP  + (long)b * 2 + j] = logp;
                out[OFF_ACT + (long)b * 2 + j] = (float)bi;
            }
            a_prev = bi;
        }
    }
}

// ---------------- LN: sum 4 split-K partials + bias, ReLU, fp16 split ----------
__global__ void __launch_bounds__(256)
ln4_relu_split_k(const float* __restrict__ Ys, const float* __restrict__ bias,
                 const float* __restrict__ g, const float* __restrict__ be,
                 __half* __restrict__ Xh, __half* __restrict__ Xl)
{
    const int wid  = threadIdx.x >> 5;
    const int lane = threadIdx.x & 31;
    const int row  = blockIdx.x * 8 + wid;
    const size_t PART = 4096L * 1024;

    const float4* r0 = (const float4*)(Ys + (size_t)row * 1024);
    const float4* r1 = (const float4*)(Ys + PART     + (size_t)row * 1024);
    const float4* r2 = (const float4*)(Ys + PART * 2 + (size_t)row * 1024);
    const float4* r3 = (const float4*)(Ys + PART * 3 + (size_t)row * 1024);

    float4 v[8];
    float s = 0.0f, q = 0.0f;
    #pragma unroll
    for (int j = 0; j < 8; j++) {
        const int i4 = lane + j * 32;
        float4 a = __ldcs(r0 + i4), b = __ldcs(r1 + i4);
        float4 c = __ldcs(r2 + i4), d = __ldcs(r3 + i4);
        float4 bs = ((const float4*)bias)[i4];
        v[j].x = a.x + b.x + c.x + d.x + bs.x;
        v[j].y = a.y + b.y + c.y + d.y + bs.y;
        v[j].z = a.z + b.z + c.z + d.z + bs.z;
        v[j].w = a.w + b.w + c.w + d.w + bs.w;
        s += v[j].x + v[j].y + v[j].z + v[j].w;
        q += v[j].x * v[j].x + v[j].y * v[j].y + v[j].z * v[j].z + v[j].w * v[j].w;
    }
    #pragma unroll
    for (int o = 16; o; o >>= 1) {
        s += __shfl_xor_sync(0xffffffffu, s, o);
        q += __shfl_xor_sync(0xffffffffu, q, o);
    }
    const float m = s * (1.0f / 1024.0f);
    const float r = rsqrtf(q * (1.0f / 1024.0f) - m * m + 1e-5f);

    __half2* xh2 = (__half2*)(Xh + (size_t)row * 1024);
    __half2* xl2 = (__half2*)(Xl + (size_t)row * 1024);
    #pragma unroll
    for (int j = 0; j < 8; j++) {
        const int i4 = lane + j * 32;
        float4 gv = ((const float4*)g)[i4];
        float4 bv = ((const float4*)be)[i4];
        float o0 = fmaxf(0.0f, (v[j].x - m) * r * gv.x + bv.x);
        float o1 = fmaxf(0.0f, (v[j].y - m) * r * gv.y + bv.y);
        float o2 = fmaxf(0.0f, (v[j].z - m) * r * gv.z + bv.z);
        float o3 = fmaxf(0.0f, (v[j].w - m) * r * gv.w + bv.w);
        __half h0 = __float2half(o0), h1 = __float2half(o1);
        __half h2 = __float2half(o2), h3 = __float2half(o3);
        xh2[i4 * 2]     = __halves2half2(h0, h1);
        xh2[i4 * 2 + 1] = __halves2half2(h2, h3);
        xl2[i4 * 2]     = __halves2half2(__float2half(o0 - __half2float(h0)),
                                         __float2half(o1 - __half2float(h1)));
        xl2[i4 * 2 + 1] = __halves2half2(__float2half(o2 - __half2float(h2)),
                                         __float2half(o3 - __half2float(h3)));
    }
}

// ---------------- launcher ----------------
extern "C" void kernel_launch(void* const* d_in, const int* in_sizes, int n_in,
                              void* d_out, int out_size)
{
    const float* obs  = (const float*)d_in[0];
    const int*   am   = (const int*)  d_in[1];
    const float* gum  = (const float*)d_in[2];
    const float* W0   = (const float*)d_in[3];
    const float* b0   = (const float*)d_in[4];
    const float* g0   = (const float*)d_in[5];
    const float* be0  = (const float*)d_in[6];
    const float* W1   = (const float*)d_in[7];
    const float* b1   = (const float*)d_in[8];
    const float* g1   = (const float*)d_in[9];
    const float* be1  = (const float*)d_in[10];
    const float* W2   = (const float*)d_in[11];
    const float* b2   = (const float*)d_in[12];
    const float* g2   = (const float*)d_in[13];
    const float* be2  = (const float*)d_in[14];
    const float* Wp   = (const float*)d_in[15];
    const float* bp   = (const float*)d_in[16];
    const float* Wv   = (const float*)d_in[17];
    const float* bv   = (const float*)d_in[18];
    float* out = (float*)d_out;

    __half *A0h, *A0l, *B0h, *B0l, *B1h, *B1l, *B2h, *B2l, *Bhh, *Bhl, *Xh, *Xl;
    float *bh, *Ys;
    cudaGetSymbolAddress((void**)&A0h, g_A0h);
    cudaGetSymbolAddress((void**)&A0l, g_A0l);
    cudaGetSymbolAddress((void**)&B0h, g_B0h);
    cudaGetSymbolAddress((void**)&B0l, g_B0l);
    cudaGetSymbolAddress((void**)&B1h, g_B1h);
    cudaGetSymbolAddress((void**)&B1l, g_B1l);
    cudaGetSymbolAddress((void**)&B2h, g_B2h);
    cudaGetSymbolAddress((void**)&B2l, g_B2l);
    cudaGetSymbolAddress((void**)&Bhh, g_Bhh);
    cudaGetSymbolAddress((void**)&Bhl, g_Bhl);
    cudaGetSymbolAddress((void**)&bh,  g_bh);
    cudaGetSymbolAddress((void**)&Ys,  g_Ys);
    cudaGetSymbolAddress((void**)&Xh,  g_Xh);
    cudaGetSymbolAddress((void**)&Xl,  g_Xl);

    const int SMEM_BIG  = 3 * (128 * 128 + 16384) + 128;   // 96 KB + pad (IM=4)
    const int SMEM_HEAD = 3 * (32 * 128 + 16384) + 128;    // 60 KB + pad (head fused)
    cudaFuncSetAttribute(gemm_hmma<4>, cudaFuncAttributeMaxDynamicSharedMemorySize, SMEM_BIG);
    cudaFuncSetAttribute(head_sample_k, cudaFuncAttributeMaxDynamicSharedMemorySize, SMEM_HEAD);

    // --- side streams/events: created ONCE, reused every call (launched work
    //     per call is byte-identical; avoids per-call pool allocation that
    //     would outlive graph teardown) ---
    static cudaStream_t s2 = nullptr, s3 = nullptr;
    static cudaEvent_t evF = nullptr, evW0 = nullptr, evS3 = nullptr;
    if (s2 == nullptr) {
        cudaStreamCreateWithFlags(&s2, cudaStreamNonBlocking);
        cudaStreamCreateWithFlags(&s3, cudaStreamNonBlocking);
        cudaEventCreateWithFlags(&evF,  cudaEventDisableTiming);
        cudaEventCreateWithFlags(&evW0, cudaEventDisableTiming);
        cudaEventCreateWithFlags(&evS3, cudaEventDisableTiming);
    }

    cudaEventRecord(evF, 0);
    cudaStreamWaitEvent(s2, evF, 0);
    cudaStreamWaitEvent(s3, evF, 0);

    // main: obs split (gates L0 via stream order)
    split_obs_k<<<4096, 256>>>(obs);

    // s2: W0 transpose (gates L0) — 64x32 tiles, half2-coalesced stores
    transpose_split_k<<<dim3(7168 / 64, 1024 / 32), dim3(32, 8), 0, s2>>>(W0, B0h, B0l, 7150, 7168, 1024);
    cudaEventRecord(evW0, s2);

    // s3: W1/W2/head prep — only needed before L1; overlaps L0 GEMM
    transpose_split_k<<<dim3(1024 / 64, 1024 / 32), dim3(32, 8), 0, s3>>>(W1, B1h, B1l, 1024, 1024, 1024);
    transpose_split_k<<<dim3(1024 / 64, 1024 / 32), dim3(32, 8), 0, s3>>>(W2, B2h, B2l, 1024, 1024, 1024);
    pack_head_k<<<(128 * 1024 + 255) / 256, 256, 0, s3>>>(Wp, bp, Wv, bv);
    cudaEventRecord(evS3, s3);

    cudaStreamWaitEvent(0, evW0, 0);

    // layer 0: split-K=4 (1024 CTAs -> ~99% SM load balance)
    gemm_hmma<4><<<dim3(8, 32, 4), 256, SMEM_BIG>>>(A0h, A0l, B0h, B0l, Ys, 1024, 7168, 56);
    ln4_relu_split_k<<<512, 256>>>(Ys, b0, g0, be0, Xh, Xl);

    cudaStreamWaitEvent(0, evS3, 0);      // W1/W2/head prep must be done by now

    // layer 1: split-K=4 (partials stay L2-resident; operands are small)
    gemm_hmma<4><<<dim3(8, 32, 4), 256, SMEM_BIG>>>(Xh, Xl, B1h, B1l, Ys, 1024, 1024, 8);
    ln4_relu_split_k<<<512, 256>>>(Ys, b1, g1, be1, Xh, Xl);
    // layer 2: split-K=4
    gemm_hmma<4><<<dim3(8, 32, 4), 256, SMEM_BIG>>>(Xh, Xl, B2h, B2l, Ys, 1024, 1024, 8);
    ln4_relu_split_k<<<512, 256>>>(Ys, b2, g2, be2, Xh, Xl);

    // fused head GEMM + sampling (BM=32 -> 128 CTAs)
    head_sample_k<<<dim3(1, 4096 / 32), 256, SMEM_HEAD>>>(Xh, Xl, Bhh, Bhl, bh, am, gum, out, 1024);
}

// round 17
// speedup vs baseline: 1.2533x; 1.0001x over previous
#include <cuda_runtime.h>
#include <cuda_fp16.h>
#include <cstdint>
#include <math.h>

#define NEGV (-1000000000.0f)
#define FLT_MAXV 3.402823466e38f

// ---------------- output layout ----------------
static const long OFF_LOGITS = 0;
static const long OFF_LP     = 385024;
static const long OFF_ACT    = 393216;
static const long OFF_VAL    = 401408;

#define SWZ128(x) ((x) ^ (((x) >> 3) & 0x70))

__device__ __forceinline__ uint32_t smem_to_u32(const void* p) {
    uint32_t a;
    asm("{ .reg .u64 t; cvta.to.shared.u64 t, %1; cvt.u32.u64 %0, t; }" : "=r"(a) : "l"(p));
    return a;
}
__device__ __forceinline__ void cp16(uint32_t sad, const void* gad) {
    asm volatile("cp.async.cg.shared.global [%0], [%1], 16;" :: "r"(sad), "l"(gad) : "memory");
}
__device__ __forceinline__ void ldm_x4(uint32_t* r, uint32_t addr) {
    asm volatile("ldmatrix.sync.aligned.m8n8.x4.shared.b16 {%0,%1,%2,%3}, [%4];"
                 : "=r"(r[0]), "=r"(r[1]), "=r"(r[2]), "=r"(r[3]) : "r"(addr));
}
__device__ __forceinline__ void mma16816(float* c, const uint32_t* a, const uint32_t* b) {
    asm volatile("mma.sync.aligned.m16n8k16.row.col.f32.f16.f16.f32 "
                 "{%0,%1,%2,%3}, {%4,%5,%6,%7}, {%8,%9}, {%0,%1,%2,%3};"
                 : "+f"(c[0]), "+f"(c[1]), "+f"(c[2]), "+f"(c[3])
                 : "r"(a[0]), "r"(a[1]), "r"(a[2]), "r"(a[3]), "r"(b[0]), "r"(b[1]));
}

// ---------------- scratch (device globals) ----------------
__device__ __half g_A0h[4096L * 7168];
__device__ __half g_A0l[4096L * 7168];
__device__ __half g_B0h[1024L * 7168];
__device__ __half g_B0l[1024L * 7168];
__device__ __half g_B1h[1024L * 1024];
__device__ __half g_B1l[1024L * 1024];
__device__ __half g_B2h[1024L * 1024];
__device__ __half g_B2l[1024L * 1024];
__device__ __half g_Bhh[128L * 1024];
__device__ __half g_Bhl[128L * 1024];
__device__ float  g_bh[128];
__device__ float  g_Ys[4L * 4096 * 1024];   // split-K partial sums
__device__ __half g_Xh[4096L * 1024];
__device__ __half g_Xl[4096L * 1024];

// ---------------- conversion kernels ----------------
// one block per row; float2 reads, half2 writes, no div/mod
__global__ void split_obs_k(const float* __restrict__ obs) {
    const int r   = blockIdx.x;
    const int tid = threadIdx.x;   // 256
    const float2* src = (const float2*)(obs + (size_t)r * 7150);   // 8B aligned
    __half2* dh = (__half2*)(g_A0h + (size_t)r * 7168);
    __half2* dl = (__half2*)(g_A0l + (size_t)r * 7168);
    #pragma unroll 4
    for (int i = tid; i < 3575; i += 256) {
        float2 v = src[i];
        __half hx = __float2half(v.x);
        __half hy = __float2half(v.y);
        dh[i] = __halves2half2(hx, hy);
        dl[i] = __halves2half2(__float2half(v.x - __half2float(hx)),
                               __float2half(v.y - __half2float(hy)));
    }
    if (tid < 9) {   // pad cols 7150..7167
        __half2 z = __float2half2_rn(0.0f);
        dh[3575 + tid] = z;
        dl[3575 + tid] = z;
    }
}

// W (K x N fp32) -> Bt hi/lo (N x Kpad fp16), transposed + split.
// 64(k) x 32(n) tile; smem n-major; half2-coalesced stores along k.
__global__ void transpose_split_k(const float* __restrict__ W,
                                  __half* __restrict__ Bh,
                                  __half* __restrict__ Bl,
                                  int K, int Kpad, int N) {
    __shared__ float t[32][65];          // [n_local][k_local]
    const int k0 = blockIdx.x * 64, n0 = blockIdx.y * 32;
    const int tx = threadIdx.x, ty = threadIdx.y;   // (32, 8)
    #pragma unroll
    for (int d = 0; d < 8; d++) {
        int ky = ty + d * 8;             // 0..63
        int k  = k0 + ky;
        t[tx][ky] = (k < K) ? W[(size_t)k * N + n0 + tx] : 0.0f;
    }
    __syncthreads();
    #pragma unroll
    for (int d = 0; d < 4; d++) {
        int nl = ty + d * 8;
        int n  = n0 + nl;
        float x0 = t[nl][2 * tx];
        float x1 = t[nl][2 * tx + 1];
        __half h0 = __float2half(x0), h1 = __float2half(x1);
        __half l0 = __float2half(x0 - __half2float(h0));
        __half l1 = __float2half(x1 - __half2float(h1));
        *(__half2*)(Bh + (size_t)n * Kpad + k0 + 2 * tx) = __halves2half2(h0, h1);
        *(__half2*)(Bl + (size_t)n * Kpad + k0 + 2 * tx) = __halves2half2(l0, l1);
    }
}

__global__ void pack_head_k(const float* __restrict__ Wp, const float* __restrict__ bp,
                            const float* __restrict__ Wv, const float* __restrict__ bv) {
    int idx = blockIdx.x * blockDim.x + threadIdx.x;
    if (idx < 128 * 1024) {
        int n = idx / 1024;
        int k = idx % 1024;
        float x = 0.0f;
        if (n < 94)       x = Wp[(size_t)k * 94 + n];
        else if (n == 94) x = Wv[k];
        __half h = __float2half(x);
        g_Bhh[idx] = h;
        g_Bhl[idx] = __float2half(x - __half2float(h));
    }
    if (idx < 128) {
        float v = 0.0f;
        if (idx < 94)       v = bp[idx];
        else if (idx == 94) v = bv[0];
        g_bh[idx] = v;
    }
}

// ---------------- HMMA GEMM: C = A(MxK) @ Bt(NxK)^T ----------------
// 3-product fp16 split: Ahi@Bhi + Alo@Bhi + Ahi@Blo (all f32-acc; R6 optimum).
// CTA tile (IM*32) x 128, 8 warps; 3-stage cp.async, SW128, XOR-folded ldmatrix.
// Split-K: blockIdx.z handles nkcSplit k-chunks; partial buffer z (stride M*N).
template<int IM>
__global__ void __launch_bounds__(256, 2)
gemm_hmma(const __half* __restrict__ Ahi, const __half* __restrict__ Alo,
          const __half* __restrict__ Bhi, const __half* __restrict__ Blo,
          float* __restrict__ C, int N, int K, int nkcSplit)
{
    constexpr int BM = IM * 32;
    constexpr uint32_t A_BYTES = (uint32_t)BM * 128;
    constexpr uint32_t SSTRIDE = A_BYTES + 16384u;

    extern __shared__ char smem_raw[];
    const uint32_t sbase = (smem_to_u32(smem_raw) + 127u) & ~127u;   // 128B aligned
    const int tid  = threadIdx.x;
    const int wid  = tid >> 5;
    const int lane = tid & 31;
    const int bm   = blockIdx.y * BM;
    const int bn   = blockIdx.x * 128;
    const int wm   = (wid >> 2) * (IM * 16);
    const int wn   = (wid & 3) * 32;

    const int niter = nkcSplit;
    const int kc0   = blockIdx.z * nkcSplit;
    C += (size_t)blockIdx.z * (size_t)(gridDim.y * BM) * N;

    float acc[IM][4][4];
    #pragma unroll
    for (int im = 0; im < IM; im++)
        #pragma unroll
        for (int in = 0; in < 4; in++)
            #pragma unroll
            for (int j = 0; j < 4; j++) acc[im][in][j] = 0.0f;

    const int ldrow = tid >> 3;
    const int j7    = tid & 7;
    const int halfv = j7 >> 2;
    const int el16  = (j7 & 3) * 8;
    const uint32_t sAoff = SWZ128((uint32_t)(ldrow * 128 + j7 * 16));
    const uint32_t sBoff = A_BYTES + SWZ128((uint32_t)(ldrow * 128 + j7 * 16));
    const __half* Ag = (halfv ? Alo : Ahi) + (size_t)(bm + ldrow) * K + el16 + ((size_t)kc0 << 5);
    const __half* Bg = (halfv ? Blo : Bhi) + (size_t)(bn + ldrow) * K + el16 + ((size_t)kc0 << 5);
    const size_t gstepA = (size_t)32 * K;

    uint32_t so_ld = 0;
    auto load_stage = [&]() {
        #pragma unroll
        for (int j = 0; j < IM; j++)
            cp16(sbase + so_ld + sAoff + (uint32_t)j * 4096u, Ag + (size_t)j * gstepA);
        #pragma unroll
        for (int j = 0; j < 4; j++)
            cp16(sbase + so_ld + sBoff + (uint32_t)j * 4096u, Bg + (size_t)j * gstepA);
        Ag += 32; Bg += 32;
        so_ld += SSTRIDE;
        if (so_ld == 3 * SSTRIDE) so_ld = 0;
    };

    const int arow = wm + (lane & 15);
    const int asub = (lane >> 4) << 4;
    const int brow = wn + (lane & 7) + ((lane >> 4) << 3);
    const int bsub = ((lane >> 3) & 1) << 4;
    uint32_t offA[IM], offB[2];
    #pragma unroll
    for (int im = 0; im < IM; im++)
        offA[im] = SWZ128((uint32_t)(((arow + im * 16) << 7) + asub));
    #pragma unroll
    for (int ib = 0; ib < 2; ib++)
        offB[ib] = A_BYTES + SWZ128((uint32_t)(((brow + ib * 16) << 7) + bsub));

    load_stage();
    asm volatile("cp.async.commit_group;" ::: "memory");
    load_stage();
    asm volatile("cp.async.commit_group;" ::: "memory");

    uint32_t so_cm = 0;
    for (int t = 0; t < niter; t++) {
        asm volatile("cp.async.wait_group 1;" ::: "memory");
        __syncthreads();

        if (t + 2 < niter) load_stage();
        asm volatile("cp.async.commit_group;" ::: "memory");

        const uint32_t sa = sbase + so_cm;
        so_cm += SSTRIDE;
        if (so_cm == 3 * SSTRIDE) so_cm = 0;

        uint32_t aA[IM], aB[2];
        #pragma unroll
        for (int im = 0; im < IM; im++) aA[im] = sa + offA[im];
        #pragma unroll
        for (int ib = 0; ib < 2; ib++)  aB[ib] = sa + offB[ib];

        #pragma unroll
        for (int ks = 0; ks < 2; ks++) {
            const uint32_t kx = ks ? 32u : 0u;
            uint32_t bh[2][4], bl[2][4];
            #pragma unroll
            for (int ib = 0; ib < 2; ib++) {
                ldm_x4(bh[ib], aB[ib] ^ kx);
                ldm_x4(bl[ib], aB[ib] ^ (kx | 64u));
            }
            {
                uint32_t ah[IM][4];
                #pragma unroll
                for (int im = 0; im < IM; im++)
                    ldm_x4(ah[im], aA[im] ^ kx);
                #pragma unroll
                for (int im = 0; im < IM; im++)
                    #pragma unroll
                    for (int in = 0; in < 4; in++)
                        mma16816(acc[im][in], ah[im], &bh[in >> 1][(in & 1) * 2]);
                #pragma unroll
                for (int im = 0; im < IM; im++)
                    #pragma unroll
                    for (int in = 0; in < 4; in++)
                        mma16816(acc[im][in], ah[im], &bl[in >> 1][(in & 1) * 2]);
            }
            {
                uint32_t al[IM][4];
                #pragma unroll
                for (int im = 0; im < IM; im++)
                    ldm_x4(al[im], aA[im] ^ (kx | 64u));
                #pragma unroll
                for (int im = 0; im < IM; im++)
                    #pragma unroll
                    for (int in = 0; in < 4; in++)
                        mma16816(acc[im][in], al[im], &bh[in >> 1][(in & 1) * 2]);
            }
        }
    }

    // epilogue: direct stores (fragment-native layout)
    #pragma unroll
    for (int in = 0; in < 4; in++) {
        int col = bn + wn + in * 8 + ((lane & 3) << 1);
        #pragma unroll
        for (int im = 0; im < IM; im++) {
            int row = bm + wm + im * 16 + (lane >> 2);
            float2 v0 = { acc[im][in][0], acc[im][in][1] };
            float2 v1 = { acc[im][in][2], acc[im][in][3] };
            *(float2*)(C + (size_t)row * N + col)       = v0;
            *(float2*)(C + (size_t)(row + 8) * N + col) = v1;
        }
    }
}

// ---------------- FUSED head GEMM + sampling ----------------
// BM=32 rows per CTA, N=128 (cols 0..93 policy, 94 value), K=1024.
__global__ void __launch_bounds__(256, 2)
head_sample_k(const __half* __restrict__ Ahi, const __half* __restrict__ Alo,
              const __half* __restrict__ Bhi, const __half* __restrict__ Blo,
              const float* __restrict__ bias,
              const int* __restrict__ mask, const float* __restrict__ gum,
              float* __restrict__ out, int K)
{
    constexpr uint32_t A_BYTES = 32u * 128u;
    constexpr uint32_t SSTRIDE = A_BYTES + 16384u;

    extern __shared__ char smem_raw[];
    const uint32_t sbase = (smem_to_u32(smem_raw) + 127u) & ~127u;
    const int tid  = threadIdx.x;
    const int wid  = tid >> 5;
    const int lane = tid & 31;
    const int bm   = blockIdx.y * 32;
    const int wm   = (wid >> 2) * 16;
    const int wn   = (wid & 3) * 32;

    const int niter = K >> 5;

    float acc[4][4];
    #pragma unroll
    for (int in = 0; in < 4; in++)
        #pragma unroll
        for (int j = 0; j < 4; j++) acc[in][j] = 0.0f;

    const int ldrow = tid >> 3;
    const int j7    = tid & 7;
    const int halfv = j7 >> 2;
    const int el16  = (j7 & 3) * 8;
    const uint32_t sAoff = SWZ128((uint32_t)(ldrow * 128 + j7 * 16));
    const uint32_t sBoff = A_BYTES + SWZ128((uint32_t)(ldrow * 128 + j7 * 16));
    const __half* Ag = (halfv ? Alo : Ahi) + (size_t)(bm + ldrow) * K + el16;
    const __half* Bg = (halfv ? Blo : Bhi) + (size_t)ldrow * K + el16;
    const size_t gstepA = (size_t)32 * K;

    uint32_t so_ld = 0;
    auto load_stage = [&]() {
        cp16(sbase + so_ld + sAoff, Ag);
        #pragma unroll
        for (int j = 0; j < 4; j++)
            cp16(sbase + so_ld + sBoff + (uint32_t)j * 4096u, Bg + (size_t)j * gstepA);
        Ag += 32; Bg += 32;
        so_ld += SSTRIDE;
        if (so_ld == 3 * SSTRIDE) so_ld = 0;
    };

    const int arow = wm + (lane & 15);
    const int asub = (lane >> 4) << 4;
    const int brow = wn + (lane & 7) + ((lane >> 4) << 3);
    const int bsub = ((lane >> 3) & 1) << 4;
    const uint32_t offA0 = SWZ128((uint32_t)((arow << 7) + asub));
    uint32_t offB[2];
    #pragma unroll
    for (int ib = 0; ib < 2; ib++)
        offB[ib] = A_BYTES + SWZ128((uint32_t)(((brow + ib * 16) << 7) + bsub));

    load_stage();
    asm volatile("cp.async.commit_group;" ::: "memory");
    load_stage();
    asm volatile("cp.async.commit_group;" ::: "memory");

    uint32_t so_cm = 0;
    for (int t = 0; t < niter; t++) {
        asm volatile("cp.async.wait_group 1;" ::: "memory");
        __syncthreads();

        if (t + 2 < niter) load_stage();
        asm volatile("cp.async.commit_group;" ::: "memory");

        const uint32_t sa = sbase + so_cm;
        so_cm += SSTRIDE;
        if (so_cm == 3 * SSTRIDE) so_cm = 0;

        uint32_t aA0 = sa + offA0;
        uint32_t aB[2];
        #pragma unroll
        for (int ib = 0; ib < 2; ib++) aB[ib] = sa + offB[ib];

        #pragma unroll
        for (int ks = 0; ks < 2; ks++) {
            const uint32_t kx = ks ? 32u : 0u;
            uint32_t bh[2][4], bl[2][4];
            #pragma unroll
            for (int ib = 0; ib < 2; ib++) {
                ldm_x4(bh[ib], aB[ib] ^ kx);
                ldm_x4(bl[ib], aB[ib] ^ (kx | 64u));
            }
            {
                uint32_t ah[4];
                ldm_x4(ah, aA0 ^ kx);
                #pragma unroll
                for (int in = 0; in < 4; in++)
                    mma16816(acc[in], ah, &bh[in >> 1][(in & 1) * 2]);
                #pragma unroll
                for (int in = 0; in < 4; in++)
                    mma16816(acc[in], ah, &bl[in >> 1][(in & 1) * 2]);
            }
            {
                uint32_t al[4];
                ldm_x4(al, aA0 ^ (kx | 64u));
                #pragma unroll
                for (int in = 0; in < 4; in++)
                    mma16816(acc[in], al, &bh[in >> 1][(in & 1) * 2]);
            }
        }
    }

    // drain all pending cp.async before smem reuse
    asm volatile("cp.async.wait_group 0;" ::: "memory");
    __syncthreads();

    // stage results to smem: 32 rows x 128 cols, stride 132 floats
    float* scr = (float*)smem_raw;
    {
        int row = wm + (lane >> 2);
        #pragma unroll
        for (int in = 0; in < 4; in++) {
            int col = wn + in * 8 + ((lane & 3) << 1);
            float bx = bias[col], by = bias[col + 1];
            *(float2*)(scr + row * 132 + col)       = make_float2(acc[in][0] + bx, acc[in][1] + by);
            *(float2*)(scr + (row + 8) * 132 + col) = make_float2(acc[in][2] + bx, acc[in][3] + by);
        }
    }
    __syncthreads();

    // sampling: warp wid handles rows wid, wid+8, wid+16, wid+24
    #pragma unroll
    for (int rr = 0; rr < 4; rr++) {
        const int row = wid + rr * 8;
        const int b   = bm + row;
        const float* lr = scr + row * 132;

        for (int a = lane; a < 94; a += 32)
            out[OFF_LOGITS + (long)b * 94 + a] = lr[a];
        if (lane == 0)
            out[OFF_VAL + b] = lr[94];

        int a_prev = -1;
        #pragma unroll
        for (int j = 0; j < 2; j++) {
            int mk[2];
            #pragma unroll
            for (int t = 0; t < 2; t++) {
                int a = lane + 32 * t;
                int m = 0;
                if (a < 47) {
                    m = mask[(long)b * 94 + j * 47 + a];
                    if (j == 1) {
                        if (a_prev >= 1 && a_prev <= 6 && a == a_prev) m = 0;
                        if (a_prev > 26 && a_prev <= 46 && a >= 27)    m = 0;
                        if (a_prev == 0 && a == 0)                     m = 0;
                    }
                }
                mk[t] = m;
            }
            if (j == 1) {
                int ssum = mk[0] + mk[1];
                #pragma unroll
                for (int off = 16; off; off >>= 1)
                    ssum += __shfl_xor_sync(0xffffffffu, ssum, off);
                if (ssum == 0 && a_prev == 0 && lane == 0) mk[0] = 1;
            }

            float lv[2], key[2];
            #pragma unroll
            for (int t = 0; t < 2; t++) {
                int a = lane + 32 * t;
                if (a < 47) {
                    float lg = lr[j * 47 + a];
                    lv[t]  = mk[t] ? lg : NEGV;
                    key[t] = lv[t] + gum[(long)b * 94 + j * 47 + a];
                } else {
                    lv[t]  = -FLT_MAXV;
                    key[t] = -FLT_MAXV;
                }
            }

            float bk = key[0]; int bi = lane;
            if (key[1] > bk) { bk = key[1]; bi = lane + 32; }
            #pragma unroll
            for (int off = 16; off; off >>= 1) {
                float ok = __shfl_xor_sync(0xffffffffu, bk, off);
                int   oi = __shfl_xor_sync(0xffffffffu, bi, off);
                if (ok > bk || (ok == bk && oi < bi)) { bk = ok; bi = oi; }
            }

            float mx = fmaxf(lv[0], lv[1]);
            #pragma unroll
            for (int off = 16; off; off >>= 1)
                mx = fmaxf(mx, __shfl_xor_sync(0xffffffffu, mx, off));
            float es = 0.0f;
            if (lane      < 47) es += expf(lv[0] - mx);
            if (lane + 32 < 47) es += expf(lv[1] - mx);
            #pragma unroll
            for (int off = 16; off; off >>= 1)
                es += __shfl_xor_sync(0xffffffffu, es, off);

            float lsel = __shfl_sync(0xffffffffu, lv[bi >= 32 ? 1 : 0], bi & 31);
            float logp = lsel - mx - logf(es);

            if (lane == 0) {
                out[OFF_LP  + (long)b * 2 + j] = logp;
                out[OFF_ACT + (long)b * 2 + j] = (float)bi;
            }
            a_prev = bi;
        }
    }
}

// ---------------- LN: sum 4 split-K partials + bias, ReLU, fp16 split ----------
// 4 warps/block, 1 row/warp, grid 1024 (better wave balance / latency hiding).
__global__ void __launch_bounds__(128)
ln4_relu_split_k(const float* __restrict__ Ys, const float* __restrict__ bias,
                 const float* __restrict__ g, const float* __restrict__ be,
                 __half* __restrict__ Xh, __half* __restrict__ Xl)
{
    const int wid  = threadIdx.x >> 5;
    const int lane = threadIdx.x & 31;
    const int row  = blockIdx.x * 4 + wid;
    const size_t PART = 4096L * 1024;

    const float4* r0 = (const float4*)(Ys + (size_t)row * 1024);
    const float4* r1 = (const float4*)(Ys + PART     + (size_t)row * 1024);
    const float4* r2 = (const float4*)(Ys + PART * 2 + (size_t)row * 1024);
    const float4* r3 = (const float4*)(Ys + PART * 3 + (size_t)row * 1024);

    float4 v[8];
    float s = 0.0f, q = 0.0f;
    #pragma unroll
    for (int j = 0; j < 8; j++) {
        const int i4 = lane + j * 32;
        float4 a = __ldcs(r0 + i4), b = __ldcs(r1 + i4);
        float4 c = __ldcs(r2 + i4), d = __ldcs(r3 + i4);
        float4 bs = ((const float4*)bias)[i4];
        v[j].x = a.x + b.x + c.x + d.x + bs.x;
        v[j].y = a.y + b.y + c.y + d.y + bs.y;
        v[j].z = a.z + b.z + c.z + d.z + bs.z;
        v[j].w = a.w + b.w + c.w + d.w + bs.w;
        s += v[j].x + v[j].y + v[j].z + v[j].w;
        q += v[j].x * v[j].x + v[j].y * v[j].y + v[j].z * v[j].z + v[j].w * v[j].w;
    }
    #pragma unroll
    for (int o = 16; o; o >>= 1) {
        s += __shfl_xor_sync(0xffffffffu, s, o);
        q += __shfl_xor_sync(0xffffffffu, q, o);
    }
    const float m = s * (1.0f / 1024.0f);
    const float r = rsqrtf(q * (1.0f / 1024.0f) - m * m + 1e-5f);

    __half2* xh2 = (__half2*)(Xh + (size_t)row * 1024);
    __half2* xl2 = (__half2*)(Xl + (size_t)row * 1024);
    #pragma unroll
    for (int j = 0; j < 8; j++) {
        const int i4 = lane + j * 32;
        float4 gv = ((const float4*)g)[i4];
        float4 bv = ((const float4*)be)[i4];
        float o0 = fmaxf(0.0f, (v[j].x - m) * r * gv.x + bv.x);
        float o1 = fmaxf(0.0f, (v[j].y - m) * r * gv.y + bv.y);
        float o2 = fmaxf(0.0f, (v[j].z - m) * r * gv.z + bv.z);
        float o3 = fmaxf(0.0f, (v[j].w - m) * r * gv.w + bv.w);
        __half h0 = __float2half(o0), h1 = __float2half(o1);
        __half h2 = __float2half(o2), h3 = __float2half(o3);
        xh2[i4 * 2]     = __halves2half2(h0, h1);
        xh2[i4 * 2 + 1] = __halves2half2(h2, h3);
        xl2[i4 * 2]     = __halves2half2(__float2half(o0 - __half2float(h0)),
                                         __float2half(o1 - __half2float(h1)));
        xl2[i4 * 2 + 1] = __halves2half2(__float2half(o2 - __half2float(h2)),
                                         __float2half(o3 - __half2float(h3)));
    }
}

// ---------------- launcher ----------------
extern "C" void kernel_launch(void* const* d_in, const int* in_sizes, int n_in,
                              void* d_out, int out_size)
{
    const float* obs  = (const float*)d_in[0];
    const int*   am   = (const int*)  d_in[1];
    const float* gum  = (const float*)d_in[2];
    const float* W0   = (const float*)d_in[3];
    const float* b0   = (const float*)d_in[4];
    const float* g0   = (const float*)d_in[5];
    const float* be0  = (const float*)d_in[6];
    const float* W1   = (const float*)d_in[7];
    const float* b1   = (const float*)d_in[8];
    const float* g1   = (const float*)d_in[9];
    const float* be1  = (const float*)d_in[10];
    const float* W2   = (const float*)d_in[11];
    const float* b2   = (const float*)d_in[12];
    const float* g2   = (const float*)d_in[13];
    const float* be2  = (const float*)d_in[14];
    const float* Wp   = (const float*)d_in[15];
    const float* bp   = (const float*)d_in[16];
    const float* Wv   = (const float*)d_in[17];
    const float* bv   = (const float*)d_in[18];
    float* out = (float*)d_out;

    __half *A0h, *A0l, *B0h, *B0l, *B1h, *B1l, *B2h, *B2l, *Bhh, *Bhl, *Xh, *Xl;
    float *bh, *Ys;
    cudaGetSymbolAddress((void**)&A0h, g_A0h);
    cudaGetSymbolAddress((void**)&A0l, g_A0l);
    cudaGetSymbolAddress((void**)&B0h, g_B0h);
    cudaGetSymbolAddress((void**)&B0l, g_B0l);
    cudaGetSymbolAddress((void**)&B1h, g_B1h);
    cudaGetSymbolAddress((void**)&B1l, g_B1l);
    cudaGetSymbolAddress((void**)&B2h, g_B2h);
    cudaGetSymbolAddress((void**)&B2l, g_B2l);
    cudaGetSymbolAddress((void**)&Bhh, g_Bhh);
    cudaGetSymbolAddress((void**)&Bhl, g_Bhl);
    cudaGetSymbolAddress((void**)&bh,  g_bh);
    cudaGetSymbolAddress((void**)&Ys,  g_Ys);
    cudaGetSymbolAddress((void**)&Xh,  g_Xh);
    cudaGetSymbolAddress((void**)&Xl,  g_Xl);

    const int SMEM_BIG  = 3 * (128 * 128 + 16384) + 128;   // 96 KB + pad (IM=4)
    const int SMEM_HEAD = 3 * (32 * 128 + 16384) + 128;    // 60 KB + pad (head fused)
    cudaFuncSetAttribute(gemm_hmma<4>, cudaFuncAttributeMaxDynamicSharedMemorySize, SMEM_BIG);
    cudaFuncSetAttribute(head_sample_k, cudaFuncAttributeMaxDynamicSharedMemorySize, SMEM_HEAD);

    // --- side streams/events: created ONCE, reused every call (launched work
    //     per call is byte-identical; avoids per-call pool allocation that
    //     would outlive graph teardown) ---
    static cudaStream_t s2 = nullptr, s3 = nullptr;
    static cudaEvent_t evF = nullptr, evW0 = nullptr, evS3 = nullptr;
    if (s2 == nullptr) {
        cudaStreamCreateWithFlags(&s2, cudaStreamNonBlocking);
        cudaStreamCreateWithFlags(&s3, cudaStreamNonBlocking);
        cudaEventCreateWithFlags(&evF,  cudaEventDisableTiming);
        cudaEventCreateWithFlags(&evW0, cudaEventDisableTiming);
        cudaEventCreateWithFlags(&evS3, cudaEventDisableTiming);
    }

    cudaEventRecord(evF, 0);
    cudaStreamWaitEvent(s2, evF, 0);
    cudaStreamWaitEvent(s3, evF, 0);

    // main: obs split (gates L0 via stream order)
    split_obs_k<<<4096, 256>>>(obs);

    // s2: W0 transpose (gates L0) — 64x32 tiles, half2-coalesced stores
    transpose_split_k<<<dim3(7168 / 64, 1024 / 32), dim3(32, 8), 0, s2>>>(W0, B0h, B0l, 7150, 7168, 1024);
    cudaEventRecord(evW0, s2);

    // s3: W1/W2/head prep — only needed before L1; overlaps L0 GEMM
    transpose_split_k<<<dim3(1024 / 64, 1024 / 32), dim3(32, 8), 0, s3>>>(W1, B1h, B1l, 1024, 1024, 1024);
    transpose_split_k<<<dim3(1024 / 64, 1024 / 32), dim3(32, 8), 0, s3>>>(W2, B2h, B2l, 1024, 1024, 1024);
    pack_head_k<<<(128 * 1024 + 255) / 256, 256, 0, s3>>>(Wp, bp, Wv, bv);
    cudaEventRecord(evS3, s3);

    cudaStreamWaitEvent(0, evW0, 0);

    // layer 0: split-K=4 (1024 CTAs -> ~99% SM load balance)
    gemm_hmma<4><<<dim3(8, 32, 4), 256, SMEM_BIG>>>(A0h, A0l, B0h, B0l, Ys, 1024, 7168, 56);
    ln4_relu_split_k<<<1024, 128>>>(Ys, b0, g0, be0, Xh, Xl);

    cudaStreamWaitEvent(0, evS3, 0);      // W1/W2/head prep must be done by now

    // layer 1: split-K=4 (partials stay L2-resident; operands are small)
    gemm_hmma<4><<<dim3(8, 32, 4), 256, SMEM_BIG>>>(Xh, Xl, B1h, B1l, Ys, 1024, 1024, 8);
    ln4_relu_split_k<<<1024, 128>>>(Ys, b1, g1, be1, Xh, Xl);
    // layer 2: split-K=4
    gemm_hmma<4><<<dim3(8, 32, 4), 256, SMEM_BIG>>>(Xh, Xl, B2h, B2l, Ys, 1024, 1024, 8);
    ln4_relu_split_k<<<1024, 128>>>(Ys, b2, g2, be2, Xh, Xl);

    // fused head GEMM + sampling (BM=32 -> 128 CTAs)
    head_sample_k<<<dim3(1, 4096 / 32), 256, SMEM_HEAD>>>(Xh, Xl, Bhh, Bhl, bh, am, gum, out, 1024);
}